// round 11
// baseline (speedup 1.0000x reference)
#include <cuda_runtime.h>
#include <math.h>

// ---------------- problem constants ----------------
#define N1 4096
#define N2 2048
#define PD 256
#define DZ 128
#define PD2 258
#define FD 772
#define EPSF 1e-12f
#define INV_TEMP 0.08838834764831843f   // 1/sqrt(128)

// ---------------- device scratch ----------------
__device__ float g_k12[N1 * 2 * DZ];   // [k1 | k2], row stride 256
__device__ float g_q[N2 * DZ];
__device__ float g_q2[N2 * DZ];
__device__ float g_q2a[N2 * DZ];
__device__ float g_q2b[N2 * DZ];
__device__ float g_S[(size_t)N2 * N1];
__device__ float g_lmfT[PD2 * N1];     // lm_feature^T [258, 4096]
__device__ float g_P[N2 * PD2];
__device__ float g_part[8 * 2048 * 258];   // split-K partials / attn2 partials alias
__device__ float g_ry[N2 * 2];             // attr @ lm_Y (cols 256,257 of prop0 numerator)
__device__ float g_rp_sx[16 * PD2];
__device__ float g_rp_sdx[16 * PD2];
__device__ float g_rp_sd[16];
__device__ float g_router0[PD2];
__device__ float g_routerp[PD2];
__device__ float g_router1[PD2];
__device__ float g_rou0[N2];
__device__ float g_rou1[N2];
__device__ float g_asum[N2];
__device__ float g_v2[N1 * 2];

// ---------------- helpers ----------------
__device__ __forceinline__ float fexp(float x) {
    float y;
    asm("ex2.approx.f32 %0, %1;" : "=f"(y) : "f"(x * 1.4426950408889634f));
    return y;
}
__device__ __forceinline__ unsigned f2tf32(float x) {
    unsigned r;
    asm("cvt.rna.tf32.f32 %0, %1;" : "=r"(r) : "f"(x));
    return r;
}
__device__ __forceinline__ void cp16(float* dst, const float* src, bool valid) {
    unsigned d = (unsigned)__cvta_generic_to_shared(dst);
    int sz = valid ? 16 : 0;
    asm volatile("cp.async.cg.shared.global [%0], [%1], 16, %2;" :: "r"(d), "l"(src), "r"(sz));
}
__device__ __forceinline__ void cp4(float* dst, const float* src, bool valid) {
    unsigned d = (unsigned)__cvta_generic_to_shared(dst);
    int sz = valid ? 4 : 0;
    asm volatile("cp.async.ca.shared.global [%0], [%1], 4, %2;" :: "r"(d), "l"(src), "r"(sz));
}
__device__ __forceinline__ void cp_commit() { asm volatile("cp.async.commit_group;"); }
template<int N_>
__device__ __forceinline__ void cp_wait() {
    asm volatile("cp.async.wait_group %0;" :: "n"(N_));
}

template<int TB>
__device__ __forceinline__ float blk_sum(float v, float* red) {
    int t = threadIdx.x;
    red[t] = v; __syncthreads();
    for (int s = TB >> 1; s > 0; s >>= 1) {
        if (t < s) red[t] += red[t + s];
        __syncthreads();
    }
    float r = red[0]; __syncthreads();
    return r;
}
template<int TB>
__device__ __forceinline__ float blk_max(float v, float* red) {
    int t = threadIdx.x;
    red[t] = v; __syncthreads();
    for (int s = TB >> 1; s > 0; s >>= 1) {
        if (t < s) red[t] = fmaxf(red[t], red[t + s]);
        __syncthreads();
    }
    float r = red[0]; __syncthreads();
    return r;
}

// ---------------- GEMM tile configs ----------------
#define BM 128
#define BN 128
#define BKT 16
#define AST 20
#define STAGES 4
#define BM6 64
#define BN6 64

// ---------------- 64x64 tf32 GEMM body ----------------
template<bool AVEC16>
__device__ __forceinline__ void gemm64_body(
    const float* __restrict__ A, int lda,
    const float* __restrict__ B, int ldb,
    const float* __restrict__ bias, float* __restrict__ C, int ldc,
    int N, int K, float scale,
    const float* __restrict__ rou1, const float* __restrict__ rt1,
    float* __restrict__ P,
    const float* __restrict__ add1, const float* __restrict__ add2,
    int bx, int by, float* smem)
{
    float* AsB = smem;
    float* BsB = smem + STAGES * BM6 * AST;

    const int tid = threadIdx.x;
    const int warp = tid >> 5, lane = tid & 31;
    const int g = lane >> 2, tig = lane & 3;
    const int wm = (warp & 1) * 32;
    const int wn = (warp >> 1) * 32;
    const int m0 = by * BM6, n0 = bx * BN6;

    const int KT = (K + BKT - 1) / BKT;

    float acc[2][4][4];
#pragma unroll
    for (int i = 0; i < 2; i++)
#pragma unroll
        for (int j = 0; j < 4; j++)
#pragma unroll
            for (int c = 0; c < 4; c++) acc[i][j][c] = 0.f;

    auto loadStage = [&](int kt, int st) {
        int k0 = kt * BKT;
        float* as = AsB + st * BM6 * AST;
        float* bs = BsB + st * BN6 * AST;
        if (AVEC16) {
#pragma unroll
            for (int p = 0; p < 2; p++) {
                int c = tid + 128 * p;
                int row = c >> 2, kq = (c & 3) * 4;
                cp16(as + row * AST + kq, A + (size_t)(m0 + row) * lda + k0 + kq, (k0 + kq) < K);
            }
#pragma unroll
            for (int p = 0; p < 2; p++) {
                int c = tid + 128 * p;
                int row = c >> 2, kq = (c & 3) * 4;
                bool v = (n0 + row) < N && (k0 + kq) < K;
                cp16(bs + row * AST + kq, B + (size_t)(n0 + row) * ldb + k0 + kq, v);
            }
        } else {
#pragma unroll
            for (int p = 0; p < 8; p++) {
                int e = tid + 128 * p;
                int row = e >> 4, kk = e & 15;
                cp4(as + row * AST + kk, A + (size_t)(m0 + row) * lda + k0 + kk, (k0 + kk) < K);
            }
#pragma unroll
            for (int p = 0; p < 8; p++) {
                int e = tid + 128 * p;
                int row = e >> 4, kk = e & 15;
                bool v = (n0 + row) < N && (k0 + kk) < K;
                cp4(bs + row * AST + kk, B + (size_t)(n0 + row) * ldb + k0 + kk, v);
            }
        }
        cp_commit();
    };

#pragma unroll
    for (int s = 0; s < STAGES - 1; s++) {
        if (s < KT) loadStage(s, s);
        else cp_commit();
    }

    for (int i = 0; i < KT; i++) {
        cp_wait<STAGES - 2>();
        __syncthreads();
        int j = i + STAGES - 1;
        if (j < KT) loadStage(j, j & (STAGES - 1));
        else cp_commit();
        const int st = i & (STAGES - 1);
        const float* as = AsB + st * BM6 * AST;
        const float* bs = BsB + st * BN6 * AST;

#pragma unroll
        for (int ks = 0; ks < 2; ks++) {
            unsigned af[2][4], bf[4][2];
#pragma unroll
            for (int mi = 0; mi < 2; mi++) {
                const float* pa = as + (wm + mi * 16 + g) * AST + ks * 8 + tig;
                af[mi][0] = f2tf32(pa[0]);
                af[mi][1] = f2tf32(pa[8 * AST]);
                af[mi][2] = f2tf32(pa[4]);
                af[mi][3] = f2tf32(pa[8 * AST + 4]);
            }
#pragma unroll
            for (int ni = 0; ni < 4; ni++) {
                const float* pb = bs + (wn + ni * 8 + g) * AST + ks * 8 + tig;
                bf[ni][0] = f2tf32(pb[0]);
                bf[ni][1] = f2tf32(pb[4]);
            }
#pragma unroll
            for (int mi = 0; mi < 2; mi++)
#pragma unroll
                for (int ni = 0; ni < 4; ni++) {
                    asm volatile(
                        "mma.sync.aligned.m16n8k8.row.col.f32.tf32.tf32.f32 "
                        "{%0,%1,%2,%3}, {%4,%5,%6,%7}, {%8,%9}, {%0,%1,%2,%3};"
                        : "+f"(acc[mi][ni][0]), "+f"(acc[mi][ni][1]),
                          "+f"(acc[mi][ni][2]), "+f"(acc[mi][ni][3])
                        : "r"(af[mi][0]), "r"(af[mi][1]), "r"(af[mi][2]), "r"(af[mi][3]),
                          "r"(bf[ni][0]), "r"(bf[ni][1]));
                }
        }
    }

#pragma unroll
    for (int mi = 0; mi < 2; mi++) {
        int mrow0 = m0 + wm + mi * 16 + g;
#pragma unroll
        for (int ni = 0; ni < 4; ni++) {
            int ncol = n0 + wn + ni * 8 + 2 * tig;
#pragma unroll
            for (int h = 0; h < 2; h++) {
                int mr = mrow0 + h * 8;
                if (ncol < N) {
                    float2 bv = bias ? *(const float2*)(bias + ncol) : make_float2(0.f, 0.f);
                    float v0 = acc[mi][ni][h * 2 + 0] * scale + bv.x;
                    float v1 = acc[mi][ni][h * 2 + 1] * scale + bv.y;
                    if (add1) {
                        float2 a1 = *(const float2*)(add1 + (size_t)mr * ldc + ncol);
                        v0 += a1.x; v1 += a1.y;
                    }
                    if (add2) {
                        float2 a2 = *(const float2*)(add2 + (size_t)mr * ldc + ncol);
                        v0 += a2.x; v1 += a2.y;
                    }
                    *(float2*)(C + (size_t)mr * ldc + ncol) = make_float2(v0, v1);
                    if (P) {
                        float rr = rou1[mr];
                        float inv = 1.f / (1.f + rr + EPSF);
                        *(float2*)(P + (size_t)mr * PD2 + ncol) =
                            make_float2((v0 + rr * rt1[ncol]) * inv,
                                        (v1 + rr * rt1[ncol + 1]) * inv);
                    }
                }
            }
        }
    }
}

// ---------------- front mega-kernel ----------------
#define BF_GEMM 384     // 128 ak + 128 pk + 64 q + 64 q2a
#define BF_TRX  256     // lm_X transpose 64x64 tiles
#define BF_TRY  64      // lm_Y -> lmfT rows 256,257
#define BF_TGX  1024    // tg_X -> out (float4)
#define BF_V2   32
#define BF_RPA  16
#define BF_ROU  16
#define BF_TOT (BF_GEMM + BF_TRX + BF_TRY + BF_TGX + BF_V2 + BF_RPA + BF_ROU)

__global__ void __launch_bounds__(128)
k_front(const float* __restrict__ lm_X, const float* __restrict__ lm_Y,
        const float* __restrict__ tg_X,
        const float* __restrict__ ak_w, const float* __restrict__ ak_b,
        const float* __restrict__ pk_w, const float* __restrict__ pk_b,
        const float* __restrict__ aq_w, const float* __restrict__ aq_b,
        const float* __restrict__ pq_w, const float* __restrict__ pq_b,
        const float* __restrict__ lm_delay, const float* __restrict__ tg_delay,
        const float* g1p, const float* g2p, const float* g3p,
        const float* ap, const float* bp,
        const float* __restrict__ pv_w, const float* __restrict__ pv_b,
        float* __restrict__ out)
{
    extern __shared__ float smem_dyn[];
    int bid = blockIdx.x, t = threadIdx.x;

    if (bid < 128) {            // k1
        gemm64_body<true>(lm_X, PD, ak_w, PD, ak_b, g_k12, 2 * DZ, DZ, PD, 1.f,
                          nullptr, nullptr, nullptr, nullptr, nullptr,
                          bid & 1, bid >> 1, smem_dyn);
        return;
    }
    bid -= 128;
    if (bid < 128) {            // k2
        gemm64_body<true>(lm_X, PD, pk_w, PD, pk_b, g_k12 + DZ, 2 * DZ, DZ, PD, 1.f,
                          nullptr, nullptr, nullptr, nullptr, nullptr,
                          bid & 1, bid >> 1, smem_dyn);
        return;
    }
    bid -= 128;
    if (bid < 64) {             // q
        gemm64_body<true>(tg_X, PD, aq_w, PD, aq_b, g_q, DZ, DZ, PD, 1.f,
                          nullptr, nullptr, nullptr, nullptr, nullptr,
                          bid & 1, bid >> 1, smem_dyn);
        return;
    }
    bid -= 64;
    if (bid < 64) {             // q2a
        gemm64_body<true>(tg_X, PD, pq_w, FD, pq_b, g_q2a, DZ, DZ, PD, 1.f,
                          nullptr, nullptr, nullptr, nullptr, nullptr,
                          bid & 1, bid >> 1, smem_dyn);
        return;
    }
    bid -= 64;
    if (bid < BF_TRX) {         // lm_X -> lmfT transpose (64x64 tiles via smem)
        float* sm = smem_dyn;   // [64][65]
        int tr = bid >> 2, tc = bid & 3;
        int r0 = tr * 64, c0 = tc * 64;
#pragma unroll
        for (int p = 0; p < 32; p++) {
            int e = t + 128 * p;
            int i = e >> 6, j = e & 63;
            sm[i * 65 + j] = lm_X[(size_t)(r0 + i) * PD + c0 + j];
        }
        __syncthreads();
#pragma unroll
        for (int p = 0; p < 32; p++) {
            int e = t + 128 * p;
            int i = e >> 6, j = e & 63;
            g_lmfT[(size_t)(c0 + i) * N1 + r0 + j] = sm[j * 65 + i];
        }
        return;
    }
    bid -= BF_TRX;
    if (bid < BF_TRY) {         // lm_Y -> lmfT rows 256,257
        int e = bid * 128 + t;
        int h = e >> 12, k = e & 4095;
        g_lmfT[(size_t)(PD + h) * N1 + k] = lm_Y[k * 2 + h];
        return;
    }
    bid -= BF_TRY;
    if (bid < BF_TGX) {         // tg_X -> out feature block (float4)
        int j4 = (bid * 128 + t) * 4;
        int r = j4 >> 8, c = j4 & 255;
        *(float4*)(out + N2 * 2 + r * FD + c) = *(const float4*)(tg_X + j4);
        return;
    }
    bid -= BF_TGX;
    if (bid < BF_V2) {          // v2 projection
        int i = bid * 128 + t;
        float y0 = lm_Y[2 * i], y1 = lm_Y[2 * i + 1];
        g_v2[2 * i]     = pv_w[0] * y0 + pv_w[1] * y1 + pv_b[0];
        g_v2[2 * i + 1] = pv_w[2] * y0 + pv_w[3] * y1 + pv_b[1];
        return;
    }
    bid -= BF_V2;
    if (bid < BF_RPA) {         // row-blocked col sums (router partials)
        int r0 = bid * 256;
        int lane = t & 31;
        float a = ap[0], b = bp[0], g1 = g1p[0];
        float ax0 = 0.f, ad0 = 0.f, ax1 = 0.f, ad1 = 0.f, ay = 0.f, ady = 0.f, sd = 0.f;
        for (int ch = 0; ch < 256; ch += 32) {
            float dl = fexp(-g1 * (a * lm_delay[r0 + ch + lane] + b));
#pragma unroll
            for (int k2 = 0; k2 < 32; k2++) {
                float d = __shfl_sync(0xffffffff, dl, k2);
                int rr = r0 + ch + k2;
                float x0 = lm_X[rr * PD + t];
                float x1 = lm_X[rr * PD + t + 128];
                ax0 += x0; ad0 += d * x0;
                ax1 += x1; ad1 += d * x1;
                if (t < 2) {
                    float y = lm_Y[rr * 2 + t];
                    ay += y; ady += d * y;
                }
                sd += d;
            }
        }
        g_rp_sx[bid * PD2 + t]        = ax0;
        g_rp_sdx[bid * PD2 + t]       = ad0;
        g_rp_sx[bid * PD2 + t + 128]  = ax1;
        g_rp_sdx[bid * PD2 + t + 128] = ad1;
        if (t < 2) {
            g_rp_sx[bid * PD2 + 256 + t]  = ay;
            g_rp_sdx[bid * PD2 + 256 + t] = ady;
        }
        if (t == 0) g_rp_sd[bid] = sd;
        return;
    }
    bid -= BF_RPA;
    {                           // rou0 / rou1
        int i = bid * 128 + t;
        float a = ap[0], b = bp[0], g2 = g2p[0], g3 = g3p[0];
        float x = a * tg_delay[i] + b;
        g_rou0[i] = fexp(-g2 * x);
        g_rou1[i] = fexp(-g3 * x);
    }
}

// ---------------- 128x128 machinery (BTRANS only) ----------------
__device__ __forceinline__ void load_stage128T(
    const float* __restrict__ A, int lda, const float* __restrict__ B, int ldb,
    float* AsB, float* BsB, int m0, int n0, int N, int K, int kt, int st, int tid)
{
    int k0 = kt * BKT;
    float* as = AsB + st * BM * AST;
#pragma unroll
    for (int p = 0; p < 2; p++) {
        int c = tid + 256 * p;
        int row = c >> 2, kq = (c & 3) * 4;
        cp16(as + row * AST + kq, A + (size_t)(m0 + row) * lda + k0 + kq, (k0 + kq) < K);
    }
    float* bs = BsB + st * BN * AST;
#pragma unroll
    for (int p = 0; p < 2; p++) {
        int c = tid + 256 * p;
        int row = c >> 2, kq = (c & 3) * 4;
        bool v = (n0 + row) < N && (k0 + kq) < K;
        cp16(bs + row * AST + kq, B + (size_t)(n0 + row) * ldb + k0 + kq, v);
    }
    cp_commit();
}

__device__ __forceinline__ void mma_ktileT(
    const float* as, const float* bsT,
    int wm, int wn, int g, int tig, float acc[4][4][4])
{
#pragma unroll
    for (int ks = 0; ks < 2; ks++) {
        unsigned af[4][4], bf[4][2];
#pragma unroll
        for (int mi = 0; mi < 4; mi++) {
            const float* pa = as + (wm + mi * 16 + g) * AST + ks * 8 + tig;
            af[mi][0] = f2tf32(pa[0]);
            af[mi][1] = f2tf32(pa[8 * AST]);
            af[mi][2] = f2tf32(pa[4]);
            af[mi][3] = f2tf32(pa[8 * AST + 4]);
        }
#pragma unroll
        for (int ni = 0; ni < 4; ni++) {
            const float* pb = bsT + (wn + ni * 8 + g) * AST + ks * 8 + tig;
            bf[ni][0] = f2tf32(pb[0]);
            bf[ni][1] = f2tf32(pb[4]);
        }
#pragma unroll
        for (int mi = 0; mi < 4; mi++)
#pragma unroll
            for (int ni = 0; ni < 4; ni++) {
                asm volatile(
                    "mma.sync.aligned.m16n8k8.row.col.f32.tf32.tf32.f32 "
                    "{%0,%1,%2,%3}, {%4,%5,%6,%7}, {%8,%9}, {%0,%1,%2,%3};"
                    : "+f"(acc[mi][ni][0]), "+f"(acc[mi][ni][1]),
                      "+f"(acc[mi][ni][2]), "+f"(acc[mi][ni][3])
                    : "r"(af[mi][0]), "r"(af[mi][1]), "r"(af[mi][2]), "r"(af[mi][3]),
                      "r"(bf[ni][0]), "r"(bf[ni][1]));
            }
    }
}

__global__ void __launch_bounds__(256)
mma_gemm(const float* __restrict__ A, int lda,
         const float* __restrict__ B, int ldb,
         float* __restrict__ C, int ldc,
         int M, int N, int K, float scale)
{
    extern __shared__ float smem_dyn[];
    float* AsB = smem_dyn;
    float* BsB = smem_dyn + STAGES * BM * AST;

    const int tid = threadIdx.x;
    const int warp = tid >> 5, lane = tid & 31;
    const int g = lane >> 2, tig = lane & 3;
    const int wm = (warp & 1) * 64;
    const int wn = (warp >> 1) * 32;
    const int m0 = blockIdx.y * BM, n0 = blockIdx.x * BN;

    const int KT = (K + BKT - 1) / BKT;
    const int SPLIT = gridDim.z;
    const int KTs = (KT + SPLIT - 1) / SPLIT;
    const int kt0 = blockIdx.z * KTs;
    const int kt1 = min(KT, kt0 + KTs);
    const int nk = kt1 - kt0;

    float acc[4][4][4];
#pragma unroll
    for (int i = 0; i < 4; i++)
#pragma unroll
        for (int j = 0; j < 4; j++)
#pragma unroll
            for (int c = 0; c < 4; c++) acc[i][j][c] = 0.f;

#pragma unroll
    for (int s = 0; s < STAGES - 1; s++) {
        if (s < nk) load_stage128T(A, lda, B, ldb, AsB, BsB, m0, n0, N, K, kt0 + s, s, tid);
        else cp_commit();
    }

    for (int i = 0; i < nk; i++) {
        cp_wait<STAGES - 2>();
        __syncthreads();
        int j = i + STAGES - 1;
        if (j < nk) load_stage128T(A, lda, B, ldb, AsB, BsB, m0, n0, N, K, kt0 + j, j & (STAGES - 1), tid);
        else cp_commit();
        const int st = i & (STAGES - 1);
        mma_ktileT(AsB + st * BM * AST, BsB + st * BN * AST, wm, wn, g, tig, acc);
    }

    float* outp = (gridDim.z > 1) ? (C + (size_t)blockIdx.z * M * N) : C;
#pragma unroll
    for (int mi = 0; mi < 4; mi++) {
        int mrow0 = m0 + wm + mi * 16 + g;
#pragma unroll
        for (int ni = 0; ni < 4; ni++) {
            int ncol = n0 + wn + ni * 8 + 2 * tig;
#pragma unroll
            for (int h = 0; h < 2; h++) {
                int mr = mrow0 + h * 8;
                if (ncol < N) {
                    *(float2*)(outp + (size_t)mr * ldc + ncol) =
                        make_float2(acc[mi][ni][h*2+0] * scale, acc[mi][ni][h*2+1] * scale);
                }
            }
        }
    }
}

// ---------------- scores2 GEMM + split softmax*v epilogue ----------------
__global__ void __launch_bounds__(256)
k_score2(const float* __restrict__ A, int lda,
         const float* __restrict__ B, int ldb,
         float* __restrict__ part, int K)
{
    extern __shared__ float smem_dyn[];
    float* AsB = smem_dyn;
    float* BsB = smem_dyn + STAGES * BM * AST;

    const int tid = threadIdx.x;
    const int warp = tid >> 5, lane = tid & 31;
    const int g = lane >> 2, tig = lane & 3;
    const int wm = (warp & 1) * 64;
    const int wn = (warp >> 1) * 32;
    const int m0 = blockIdx.y * BM, n0 = blockIdx.x * BN;
    const int KT = K / BKT;

    float acc[4][4][4];
#pragma unroll
    for (int i = 0; i < 4; i++)
#pragma unroll
        for (int j = 0; j < 4; j++)
#pragma unroll
            for (int c = 0; c < 4; c++) acc[i][j][c] = 0.f;

#pragma unroll
    for (int s = 0; s < STAGES - 1; s++) {
        if (s < KT) load_stage128T(A, lda, B, ldb, AsB, BsB, m0, n0, N1, K, s, s, tid);
        else cp_commit();
    }
    for (int i = 0; i < KT; i++) {
        cp_wait<STAGES - 2>();
        __syncthreads();
        int j = i + STAGES - 1;
        if (j < KT) load_stage128T(A, lda, B, ldb, AsB, BsB, m0, n0, N1, K, j, j & (STAGES - 1), tid);
        else cp_commit();
        const int st = i & (STAGES - 1);
        mma_ktileT(AsB + st * BM * AST, BsB + st * BN * AST, wm, wn, g, tig, acc);
    }

    float v2x[4][2], v2y[4][2];
#pragma unroll
    for (int ni = 0; ni < 4; ni++) {
#pragma unroll
        for (int w = 0; w < 2; w++) {
            int gc = n0 + wn + ni * 8 + 2 * tig + w;
            v2x[ni][w] = g_v2[2 * gc];
            v2y[ni][w] = g_v2[2 * gc + 1];
        }
    }

    __syncthreads();
    float* sred = smem_dyn;
    const int w2 = warp >> 1;
#pragma unroll
    for (int mi = 0; mi < 4; mi++) {
#pragma unroll
        for (int h = 0; h < 2; h++) {
            int rloc = wm + mi * 16 + g + 8 * h;
            float m = -1e30f;
#pragma unroll
            for (int ni = 0; ni < 4; ni++)
#pragma unroll
                for (int w = 0; w < 2; w++)
                    m = fmaxf(m, acc[mi][ni][h * 2 + w] * INV_TEMP);
            float sw = 0.f, s0 = 0.f, s1 = 0.f;
#pragma unroll
            for (int ni = 0; ni < 4; ni++)
#pragma unroll
                for (int w = 0; w < 2; w++) {
                    float e = fexp(acc[mi][ni][h * 2 + w] * INV_TEMP - m);
                    sw += e;
                    s0 += e * v2x[ni][w];
                    s1 += e * v2y[ni][w];
                }
#pragma unroll
            for (int off = 1; off < 4; off <<= 1) {
                float om  = __shfl_xor_sync(0xffffffff, m,  off);
                float osw = __shfl_xor_sync(0xffffffff, sw, off);
                float os0 = __shfl_xor_sync(0xffffffff, s0, off);
                float os1 = __shfl_xor_sync(0xffffffff, s1, off);
                float nm = fmaxf(m, om);
                float ea = fexp(m - nm), eb = fexp(om - nm);
                sw = sw * ea + osw * eb;
                s0 = s0 * ea + os0 * eb;
                s1 = s1 * ea + os1 * eb;
                m = nm;
            }
            if (tig == 0) {
                float* p = sred + ((w2 * BM) + rloc) * 4;
                p[0] = m; p[1] = sw; p[2] = s0; p[3] = s1;
            }
        }
    }
    __syncthreads();

    if (tid < BM) {
        float m = -1e30f, sw = 0.f, s0 = 0.f, s1 = 0.f;
#pragma unroll
        for (int w = 0; w < 4; w++) {
            const float* p = sred + ((w * BM) + tid) * 4;
            float om = p[0], osw = p[1], os0 = p[2], os1 = p[3];
            float nm = fmaxf(m, om);
            float ea = fexp(m - nm), eb = fexp(om - nm);
            sw = sw * ea + osw * eb;
            s0 = s0 * ea + os0 * eb;
            s1 = s1 * ea + os1 * eb;
            m = nm;
        }
        float* p = part + ((size_t)blockIdx.x * N2 + (m0 + tid)) * 4;
        p[0] = m; p[1] = sw; p[2] = s0; p[3] = s1;
    }
}

__global__ void k_comb2(const float* __restrict__ part, float* __restrict__ out) {
    int r = blockIdx.x * blockDim.x + threadIdx.x;
    if (r < N2) {
        float m = -1e30f, sw = 0.f, s0 = 0.f, s1 = 0.f;
        for (int cb = 0; cb < 32; cb++) {
            const float* p = part + ((size_t)cb * N2 + r) * 4;
            float om = p[0], osw = p[1], os0 = p[2], os1 = p[3];
            float nm = fmaxf(m, om);
            float ea = fexp(m - nm), eb = fexp(om - nm);
            sw = sw * ea + osw * eb;
            s0 = s0 * ea + os0 * eb;
            s1 = s1 * ea + os1 * eb;
            m = nm;
        }
        out[2 * r]     = s0 / sw;
        out[2 * r + 1] = s1 / sw;
    }
}

// ---------------- attention 1 softmax + fused attr@lm_Y (+router combine) -----
__global__ void k_attr(const float* __restrict__ lm_Y) {
    __shared__ float red[256];
    int t = threadIdx.x;
    if (blockIdx.x == N2) {
        float sd = 0.f;
#pragma unroll
        for (int rb = 0; rb < 16; rb++) sd += g_rp_sd[rb];
        for (int c = t; c < PD2; c += 256) {
            float sx = 0.f, sdx = 0.f;
#pragma unroll
            for (int rb = 0; rb < 16; rb++) {
                sx  += g_rp_sx[rb * PD2 + c];
                sdx += g_rp_sdx[rb * PD2 + c];
            }
            float r0v = sx * (1.0f / N1);
            g_router0[c] = r0v;
            g_routerp[c] = (sdx + r0v) / (1.f + sd + EPSF);
        }
        return;
    }
    int r = blockIdx.x;
    float* s = g_S + (size_t)r * N1;
    float e[16];
    float m = -1e30f;
#pragma unroll
    for (int i = 0; i < 4; i++) {
        float4 v = *(const float4*)(s + t * 4 + i * 1024);
        e[i*4+0] = v.x; e[i*4+1] = v.y; e[i*4+2] = v.z; e[i*4+3] = v.w;
        m = fmaxf(fmaxf(fmaxf(m, v.x), fmaxf(v.y, v.z)), v.w);
    }
    m = blk_max<256>(m, red);
    float z = 0.f;
#pragma unroll
    for (int i = 0; i < 16; i++) { e[i] = fexp(e[i] - m); z += e[i]; }
    z = blk_sum<256>(z, red);
    float inv = 1.f / z;
    float rs = 0.f, ry0 = 0.f, ry1 = 0.f;
#pragma unroll
    for (int i = 0; i < 4; i++) {
        int base = t * 4 + i * 1024;
        float4 v;
        v.x = fexp(e[i*4+0] * inv);
        v.y = fexp(e[i*4+1] * inv);
        v.z = fexp(e[i*4+2] * inv);
        v.w = fexp(e[i*4+3] * inv);
        *(float4*)(s + base) = v;
        rs += v.x + v.y + v.z + v.w;
        float4 y01 = *(const float4*)(lm_Y + base * 2);
        float4 y23 = *(const float4*)(lm_Y + base * 2 + 4);
        ry0 += v.x * y01.x + v.y * y01.z + v.z * y23.x + v.w * y23.z;
        ry1 += v.x * y01.y + v.y * y01.w + v.z * y23.y + v.w * y23.w;
    }
    rs  = blk_sum<256>(rs, red);
    ry0 = blk_sum<256>(ry0, red);
    ry1 = blk_sum<256>(ry1, red);
    if (t == 0) {
        g_asum[r] = rs;
        g_ry[2 * r]     = ry0;
        g_ry[2 * r + 1] = ry1;
    }
}

// ---------------- fused reduce(attr@lmfT, split-8) + prop0 (+router1 block) ----
__global__ void k_fuse1(const float* __restrict__ part, const float* __restrict__ tg_X,
                        const float* __restrict__ w1_w, const float* __restrict__ w1_b) {
    if (blockIdx.x == 2064) {
        int t = threadIdx.x;
        int warp = t >> 5, lane = t & 31;
        for (int j = warp; j < PD2; j += 8) {
            float s = 0.f;
            for (int k = lane; k < PD2; k += 32) s += g_routerp[k] * w1_w[j * PD2 + k];
#pragma unroll
            for (int off = 16; off > 0; off >>= 1) s += __shfl_xor_sync(0xffffffff, s, off);
            if (lane == 0) g_router1[j] = s + w1_b[j];
        }
        return;
    }
    int i = blockIdx.x * blockDim.x + threadIdx.x;
    if (i < N2 * PD2) {
        int r = i / PD2, c = i - r * PD2;
        float s;
        if (c < PD) {
            s = 0.f;
#pragma unroll
            for (int z = 0; z < 8; z++) s += part[(size_t)z * N2 * PD + r * PD + c];
            s += tg_X[r * PD + c];
        } else {
            s = g_ry[2 * r + (c - PD)];
        }
        float num = s + g_rou0[r] * g_router0[c];
        g_P[i] = num / (1.f + g_asum[r] + g_rou0[r] + EPSF);
    }
}

// ---------------- 64-tile wrappers ----------------
__global__ void __launch_bounds__(128)
k_f1(const float* __restrict__ w1_w, const float* __restrict__ w1_b, float* __restrict__ out) {
    extern __shared__ float smem_dyn[];
    int bx = blockIdx.x % 5, by = blockIdx.x / 5;
    gemm64_body<false>(g_P, PD2, w1_w, PD2, w1_b, out + N2 * 2 + PD, FD, PD2, PD2, 1.f,
                       g_rou1, g_router1, g_P, nullptr, nullptr, bx, by, smem_dyn);
}

__global__ void __launch_bounds__(128)
k_mid(const float* __restrict__ w2_w, const float* __restrict__ w2_b,
      const float* __restrict__ pq_w, float* __restrict__ out) {
    extern __shared__ float smem_dyn[];
    if (blockIdx.x < 160) {
        int bx = blockIdx.x % 5, by = blockIdx.x / 5;
        gemm64_body<false>(g_P, PD2, w2_w, PD2, w2_b, out + N2 * 2 + PD + PD2, FD, PD2, PD2, 1.f,
                           nullptr, nullptr, nullptr, nullptr, nullptr, bx, by, smem_dyn);
    } else {
        int b = blockIdx.x - 160;
        gemm64_body<false>(out + N2 * 2 + PD, FD, pq_w + PD, FD, nullptr, g_q2b, DZ, DZ, PD2, 1.f,
                           nullptr, nullptr, nullptr, nullptr, nullptr, b & 1, b >> 1, smem_dyn);
    }
}

__global__ void __launch_bounds__(128)
k_q2fin(const float* __restrict__ pq_w, const float* __restrict__ out) {
    extern __shared__ float smem_dyn[];
    gemm64_body<false>(out + N2 * 2 + PD + PD2, FD, pq_w + PD + PD2, FD, nullptr, g_q2, DZ, DZ, PD2, 1.f,
                       nullptr, nullptr, nullptr, g_q2a, g_q2b, blockIdx.x & 1, blockIdx.x >> 1, smem_dyn);
}

// ---------------- host launch ----------------
static float* sym_addr(const void* s) {
    void* p = nullptr;
    cudaGetSymbolAddress(&p, s);
    return (float*)p;
}

#define SMEM_TT ((STAGES * BM * AST + STAGES * BN * AST) * 4)
#define SMEM_64 ((STAGES * BM6 * AST * 2) * 4)

extern "C" void kernel_launch(void* const* d_in, const int* in_sizes, int n_in,
                              void* d_out, int out_size) {
    const float* lm_X    = (const float*)d_in[0];
    const float* lm_Y    = (const float*)d_in[1];
    const float* tg_X    = (const float*)d_in[2];
    const float* lm_delay= (const float*)d_in[4];
    const float* tg_delay= (const float*)d_in[5];
    const float* aq_w    = (const float*)d_in[6];
    const float* aq_b    = (const float*)d_in[7];
    const float* ak_w    = (const float*)d_in[8];
    const float* ak_b    = (const float*)d_in[9];
    const float* w1_w    = (const float*)d_in[10];
    const float* w1_b    = (const float*)d_in[11];
    const float* w2_w    = (const float*)d_in[12];
    const float* w2_b    = (const float*)d_in[13];
    const float* pq_w    = (const float*)d_in[14];
    const float* pq_b    = (const float*)d_in[15];
    const float* pk_w    = (const float*)d_in[16];
    const float* pk_b    = (const float*)d_in[17];
    const float* pv_w    = (const float*)d_in[18];
    const float* pv_b    = (const float*)d_in[19];
    const float* gamma1  = (const float*)d_in[20];
    const float* gamma2  = (const float*)d_in[21];
    const float* gamma3  = (const float*)d_in[22];
    const float* alpha   = (const float*)d_in[23];
    const float* beta    = (const float*)d_in[24];
    float* out = (float*)d_out;

    float* pk12  = sym_addr(g_k12);
    float* pq    = sym_addr(g_q);
    float* pq2   = sym_addr(g_q2);
    float* pS    = sym_addr(g_S);
    float* plmfT = sym_addr(g_lmfT);
    float* pPart = sym_addr(g_part);

    cudaFuncSetAttribute(mma_gemm, cudaFuncAttributeMaxDynamicSharedMemorySize, SMEM_TT);
    cudaFuncSetAttribute(k_score2, cudaFuncAttributeMaxDynamicSharedMemorySize, SMEM_TT);
    cudaFuncSetAttribute(k_front,  cudaFuncAttributeMaxDynamicSharedMemorySize, SMEM_64);
    cudaFuncSetAttribute(k_f1,     cudaFuncAttributeMaxDynamicSharedMemorySize, SMEM_64);
    cudaFuncSetAttribute(k_mid,    cudaFuncAttributeMaxDynamicSharedMemorySize, SMEM_64);
    cudaFuncSetAttribute(k_q2fin,  cudaFuncAttributeMaxDynamicSharedMemorySize, SMEM_64);

    dim3 blk(256), blk64(128);

    // 1. front mega-kernel: projections (k1,k2,q,q2a) + transpose + prep
    k_front<<<BF_TOT, blk64, SMEM_64>>>(lm_X, lm_Y, tg_X, ak_w, ak_b, pk_w, pk_b,
                                        aq_w, aq_b, pq_w, pq_b, lm_delay, tg_delay,
                                        gamma1, gamma2, gamma3, alpha, beta,
                                        pv_w, pv_b, out);

    // 2. scores1 = q @ k1^T
    mma_gemm<<<dim3(32, 16, 1), blk, SMEM_TT>>>(pq, DZ, pk12, 2 * DZ, pS, N1, N2, N1, DZ, INV_TEMP);

    // 3. softmax -> attr + fused attr@lm_Y (+ router combine)
    k_attr<<<N2 + 1, blk>>>(lm_Y);

    // 4. attr @ lmfT[:256] (BTRANS, vectorized), split-8 -> 256 CTAs
    mma_gemm<<<dim3(2, 16, 8), blk, SMEM_TT>>>(pS, N1, plmfT, N1, pPart, PD, N2, PD, N1, 1.f);

    // 5. fused reduce(8) + prop0 (+ router1 block)
    k_fuse1<<<2065, blk>>>(pPart, tg_X, w1_w, w1_b);

    // 6. f1 -> out, fused prop1
    k_f1<<<160, blk64, SMEM_64>>>(w1_w, w1_b, out);

    // 7. batched f2 + q2b
    k_mid<<<224, blk64, SMEM_64>>>(w2_w, w2_b, pq_w, out);

    // 8. q2 = q2a + q2b + q2c
    k_q2fin<<<64, blk64, SMEM_64>>>(pq_w, out);

    // 9-10. attention 2 fused
    k_score2<<<dim3(32, 16, 1), blk, SMEM_TT>>>(pq2, DZ, pk12 + DZ, 2 * DZ, pPart, DZ);
    k_comb2<<<8, blk>>>(pPart, out);
}

// round 12
// speedup vs baseline: 1.0859x; 1.0859x over previous
#include <cuda_runtime.h>
#include <math.h>

// ---------------- problem constants ----------------
#define N1 4096
#define N2 2048
#define PD 256
#define DZ 128
#define PD2 258
#define PDP 264            // padded K stride (16B-aligned rows)
#define FD 772
#define EPSF 1e-12f
#define INV_TEMP 0.08838834764831843f

// ---------------- device scratch ----------------
__device__ float g_k12[N1 * 2 * DZ];
__device__ float g_q[N2 * DZ];
__device__ float g_q2[N2 * DZ];
__device__ float g_q2a[N2 * DZ];
__device__ float g_q2b[N2 * DZ];
__device__ float g_S[(size_t)N2 * N1];
__device__ float g_lmfT[PD2 * N1];
__device__ float g_Pa[N2 * PDP];           // prop0 (rounded, padded)
__device__ float g_Pb[N2 * PDP];           // prop1 (rounded, padded)
__device__ float g_f1p[N2 * PDP];          // rounded padded f1 copy
__device__ float g_f2p[N2 * PDP];          // rounded padded f2 copy
__device__ float g_w1p[PD2 * PDP];
__device__ float g_w2p[PD2 * PDP];
__device__ float g_pqbp[DZ * PDP];
__device__ float g_pqcp[DZ * PDP];
__device__ float g_part[8 * 2048 * 258];
__device__ float g_ry[N2 * 2];
__device__ float g_rp_sx[16 * PD2];
__device__ float g_rp_sdx[16 * PD2];
__device__ float g_rp_sd[16];
__device__ float g_router0[PD2];
__device__ float g_routerp[PD2];
__device__ float g_router1[PD2];
__device__ float g_rou0[N2];
__device__ float g_rou1[N2];
__device__ float g_asum[N2];
__device__ float g_v2[N1 * 2];

// ---------------- helpers ----------------
__device__ __forceinline__ float fexp(float x) {
    float y;
    asm("ex2.approx.f32 %0, %1;" : "=f"(y) : "f"(x * 1.4426950408889634f));
    return y;
}
__device__ __forceinline__ float rtf32(float x) {
    unsigned r;
    asm("cvt.rna.tf32.f32 %0, %1;" : "=r"(r) : "f"(x));
    return __uint_as_float(r);
}
__device__ __forceinline__ unsigned f2tf32(float x) {
    unsigned r;
    asm("cvt.rna.tf32.f32 %0, %1;" : "=r"(r) : "f"(x));
    return r;
}
__device__ __forceinline__ void cp16(float* dst, const float* src, bool valid) {
    unsigned d = (unsigned)__cvta_generic_to_shared(dst);
    int sz = valid ? 16 : 0;
    asm volatile("cp.async.cg.shared.global [%0], [%1], 16, %2;" :: "r"(d), "l"(src), "r"(sz));
}
__device__ __forceinline__ void cp_commit() { asm volatile("cp.async.commit_group;"); }
template<int N_>
__device__ __forceinline__ void cp_wait() {
    asm volatile("cp.async.wait_group %0;" :: "n"(N_));
}

template<int TB>
__device__ __forceinline__ float blk_sum(float v, float* red) {
    int t = threadIdx.x;
    red[t] = v; __syncthreads();
    for (int s = TB >> 1; s > 0; s >>= 1) {
        if (t < s) red[t] += red[t + s];
        __syncthreads();
    }
    float r = red[0]; __syncthreads();
    return r;
}
template<int TB>
__device__ __forceinline__ float blk_max(float v, float* red) {
    int t = threadIdx.x;
    red[t] = v; __syncthreads();
    for (int s = TB >> 1; s > 0; s >>= 1) {
        if (t < s) red[t] = fmaxf(red[t], red[t + s]);
        __syncthreads();
    }
    float r = red[0]; __syncthreads();
    return r;
}

// ---------------- GEMM tile configs ----------------
#define BM 128
#define BN 128
#define BKT 16
#define AST 20
#define STAGES 4
#define BM6 64
#define BN6 64

// ---------------- 64x64 tf32 GEMM body ----------------
// CVT: convert fragments to tf32 in mainloop (for raw-fp32 operands).
// Kld: load-valid bound (>= K for zero-padded operands).
template<bool CVT>
__device__ __forceinline__ void gemm64_body(
    const float* __restrict__ A, int lda,
    const float* __restrict__ B, int ldb,
    const float* __restrict__ bias, float* __restrict__ C, int ldc,
    int N, int K, int Kld, float scale,
    const float* __restrict__ rou1, const float* __restrict__ rt1,
    float* __restrict__ P, float* __restrict__ Cpad,
    const float* __restrict__ add1, const float* __restrict__ add2,
    bool roundC, int bx, int by, float* smem)
{
    float* AsB = smem;
    float* BsB = smem + STAGES * BM6 * AST;

    const int tid = threadIdx.x;
    const int warp = tid >> 5, lane = tid & 31;
    const int g = lane >> 2, tig = lane & 3;
    const int wm = (warp & 1) * 32;
    const int wn = (warp >> 1) * 32;
    const int m0 = by * BM6, n0 = bx * BN6;

    const int KT = (K + BKT - 1) / BKT;

    float acc[2][4][4];
#pragma unroll
    for (int i = 0; i < 2; i++)
#pragma unroll
        for (int j = 0; j < 4; j++)
#pragma unroll
            for (int c = 0; c < 4; c++) acc[i][j][c] = 0.f;

    auto loadStage = [&](int kt, int st) {
        int k0 = kt * BKT;
        float* as = AsB + st * BM6 * AST;
        float* bs = BsB + st * BN6 * AST;
#pragma unroll
        for (int p = 0; p < 2; p++) {
            int c = tid + 128 * p;
            int row = c >> 2, kq = (c & 3) * 4;
            cp16(as + row * AST + kq, A + (size_t)(m0 + row) * lda + k0 + kq, (k0 + kq) < Kld);
        }
#pragma unroll
        for (int p = 0; p < 2; p++) {
            int c = tid + 128 * p;
            int row = c >> 2, kq = (c & 3) * 4;
            bool v = (n0 + row) < N && (k0 + kq) < Kld;
            cp16(bs + row * AST + kq, B + (size_t)(n0 + row) * ldb + k0 + kq, v);
        }
        cp_commit();
    };

#pragma unroll
    for (int s = 0; s < STAGES - 1; s++) {
        if (s < KT) loadStage(s, s);
        else cp_commit();
    }

    for (int i = 0; i < KT; i++) {
        cp_wait<STAGES - 2>();
        __syncthreads();
        int j = i + STAGES - 1;
        if (j < KT) loadStage(j, j & (STAGES - 1));
        else cp_commit();
        const int st = i & (STAGES - 1);
        const float* as = AsB + st * BM6 * AST;
        const float* bs = BsB + st * BN6 * AST;

#pragma unroll
        for (int ks = 0; ks < 2; ks++) {
            unsigned af[2][4], bf[4][2];
#pragma unroll
            for (int mi = 0; mi < 2; mi++) {
                const float* pa = as + (wm + mi * 16 + g) * AST + ks * 8 + tig;
                if (CVT) {
                    af[mi][0] = f2tf32(pa[0]);
                    af[mi][1] = f2tf32(pa[8 * AST]);
                    af[mi][2] = f2tf32(pa[4]);
                    af[mi][3] = f2tf32(pa[8 * AST + 4]);
                } else {
                    af[mi][0] = __float_as_uint(pa[0]);
                    af[mi][1] = __float_as_uint(pa[8 * AST]);
                    af[mi][2] = __float_as_uint(pa[4]);
                    af[mi][3] = __float_as_uint(pa[8 * AST + 4]);
                }
            }
#pragma unroll
            for (int ni = 0; ni < 4; ni++) {
                const float* pb = bs + (wn + ni * 8 + g) * AST + ks * 8 + tig;
                if (CVT) {
                    bf[ni][0] = f2tf32(pb[0]);
                    bf[ni][1] = f2tf32(pb[4]);
                } else {
                    bf[ni][0] = __float_as_uint(pb[0]);
                    bf[ni][1] = __float_as_uint(pb[4]);
                }
            }
#pragma unroll
            for (int mi = 0; mi < 2; mi++)
#pragma unroll
                for (int ni = 0; ni < 4; ni++) {
                    asm volatile(
                        "mma.sync.aligned.m16n8k8.row.col.f32.tf32.tf32.f32 "
                        "{%0,%1,%2,%3}, {%4,%5,%6,%7}, {%8,%9}, {%0,%1,%2,%3};"
                        : "+f"(acc[mi][ni][0]), "+f"(acc[mi][ni][1]),
                          "+f"(acc[mi][ni][2]), "+f"(acc[mi][ni][3])
                        : "r"(af[mi][0]), "r"(af[mi][1]), "r"(af[mi][2]), "r"(af[mi][3]),
                          "r"(bf[ni][0]), "r"(bf[ni][1]));
                }
        }
    }

#pragma unroll
    for (int mi = 0; mi < 2; mi++) {
        int mrow0 = m0 + wm + mi * 16 + g;
#pragma unroll
        for (int ni = 0; ni < 4; ni++) {
            int ncol = n0 + wn + ni * 8 + 2 * tig;
#pragma unroll
            for (int h = 0; h < 2; h++) {
                int mr = mrow0 + h * 8;
                if (ncol < N) {
                    float2 bv = bias ? *(const float2*)(bias + ncol) : make_float2(0.f, 0.f);
                    float v0 = acc[mi][ni][h * 2 + 0] * scale + bv.x;
                    float v1 = acc[mi][ni][h * 2 + 1] * scale + bv.y;
                    if (add1) {
                        float2 a1 = *(const float2*)(add1 + (size_t)mr * ldc + ncol);
                        v0 += a1.x; v1 += a1.y;
                    }
                    if (add2) {
                        float2 a2 = *(const float2*)(add2 + (size_t)mr * ldc + ncol);
                        v0 += a2.x; v1 += a2.y;
                    }
                    float c0 = roundC ? rtf32(v0) : v0;
                    float c1 = roundC ? rtf32(v1) : v1;
                    *(float2*)(C + (size_t)mr * ldc + ncol) = make_float2(c0, c1);
                    if (Cpad) {
                        *(float2*)(Cpad + (size_t)mr * PDP + ncol) =
                            make_float2(rtf32(v0), rtf32(v1));
                    }
                    if (P) {
                        float rr = rou1[mr];
                        float inv = 1.f / (1.f + rr + EPSF);
                        *(float2*)(P + (size_t)mr * PDP + ncol) =
                            make_float2(rtf32((v0 + rr * rt1[ncol]) * inv),
                                        rtf32((v1 + rr * rt1[ncol + 1]) * inv));
                    }
                }
            }
        }
    }
}

// ---------------- front mega-kernel ----------------
#define BF_GEMM 384
#define BF_TRX  256
#define BF_TRY  64
#define BF_TGX  1024
#define BF_V2   32
#define BF_RPA  16
#define BF_ROU  16
#define BF_WP   1065   // 2*258*264 / 128 (ceil)
#define BF_PQP  528    // 2*128*264 / 128
#define BF_ZP   288    // 3*2048*6 / 128
#define BF_TOT (BF_GEMM + BF_TRX + BF_TRY + BF_TGX + BF_V2 + BF_RPA + BF_ROU + BF_WP + BF_PQP + BF_ZP)

__global__ void __launch_bounds__(128)
k_front(const float* __restrict__ lm_X, const float* __restrict__ lm_Y,
        const float* __restrict__ tg_X,
        const float* __restrict__ ak_w, const float* __restrict__ ak_b,
        const float* __restrict__ pk_w, const float* __restrict__ pk_b,
        const float* __restrict__ aq_w, const float* __restrict__ aq_b,
        const float* __restrict__ pq_w, const float* __restrict__ pq_b,
        const float* __restrict__ w1_w, const float* __restrict__ w2_w,
        const float* __restrict__ lm_delay, const float* __restrict__ tg_delay,
        const float* g1p, const float* g2p, const float* g3p,
        const float* ap, const float* bp,
        const float* __restrict__ pv_w, const float* __restrict__ pv_b,
        float* __restrict__ out)
{
    extern __shared__ float smem_dyn[];
    int bid = blockIdx.x, t = threadIdx.x;

    if (bid < 128) {            // k1 (rounded)
        gemm64_body<true>(lm_X, PD, ak_w, PD, ak_b, g_k12, 2 * DZ, DZ, PD, PD, 1.f,
                          nullptr, nullptr, nullptr, nullptr, nullptr, nullptr,
                          true, bid & 1, bid >> 1, smem_dyn);
        return;
    }
    bid -= 128;
    if (bid < 128) {            // k2 (rounded)
        gemm64_body<true>(lm_X, PD, pk_w, PD, pk_b, g_k12 + DZ, 2 * DZ, DZ, PD, PD, 1.f,
                          nullptr, nullptr, nullptr, nullptr, nullptr, nullptr,
                          true, bid & 1, bid >> 1, smem_dyn);
        return;
    }
    bid -= 128;
    if (bid < 64) {             // q (rounded)
        gemm64_body<true>(tg_X, PD, aq_w, PD, aq_b, g_q, DZ, DZ, PD, PD, 1.f,
                          nullptr, nullptr, nullptr, nullptr, nullptr, nullptr,
                          true, bid & 1, bid >> 1, smem_dyn);
        return;
    }
    bid -= 64;
    if (bid < 64) {             // q2a (exact fp32, summed later)
        gemm64_body<true>(tg_X, PD, pq_w, FD, pq_b, g_q2a, DZ, DZ, PD, PD, 1.f,
                          nullptr, nullptr, nullptr, nullptr, nullptr, nullptr,
                          false, bid & 1, bid >> 1, smem_dyn);
        return;
    }
    bid -= 64;
    if (bid < BF_TRX) {         // lm_X -> lmfT transpose (rounded)
        float* sm = smem_dyn;   // [64][65]
        int tr = bid >> 2, tc = bid & 3;
        int r0 = tr * 64, c0 = tc * 64;
#pragma unroll
        for (int p = 0; p < 32; p++) {
            int e = t + 128 * p;
            int i = e >> 6, j = e & 63;
            sm[i * 65 + j] = lm_X[(size_t)(r0 + i) * PD + c0 + j];
        }
        __syncthreads();
#pragma unroll
        for (int p = 0; p < 32; p++) {
            int e = t + 128 * p;
            int i = e >> 6, j = e & 63;
            g_lmfT[(size_t)(c0 + i) * N1 + r0 + j] = rtf32(sm[j * 65 + i]);
        }
        return;
    }
    bid -= BF_TRX;
    if (bid < BF_TRY) {         // lm_Y -> lmfT rows 256,257 (rounded)
        int e = bid * 128 + t;
        int h = e >> 12, k = e & 4095;
        g_lmfT[(size_t)(PD + h) * N1 + k] = rtf32(lm_Y[k * 2 + h]);
        return;
    }
    bid -= BF_TRY;
    if (bid < BF_TGX) {         // tg_X -> out feature block
        int j4 = (bid * 128 + t) * 4;
        int r = j4 >> 8, c = j4 & 255;
        *(float4*)(out + N2 * 2 + r * FD + c) = *(const float4*)(tg_X + j4);
        return;
    }
    bid -= BF_TGX;
    if (bid < BF_V2) {          // v2 projection
        int i = bid * 128 + t;
        float y0 = lm_Y[2 * i], y1 = lm_Y[2 * i + 1];
        g_v2[2 * i]     = pv_w[0] * y0 + pv_w[1] * y1 + pv_b[0];
        g_v2[2 * i + 1] = pv_w[2] * y0 + pv_w[3] * y1 + pv_b[1];
        return;
    }
    bid -= BF_V2;
    if (bid < BF_RPA) {         // row-blocked col sums
        int r0 = bid * 256;
        int lane = t & 31;
        float a = ap[0], b = bp[0], g1 = g1p[0];
        float ax0 = 0.f, ad0 = 0.f, ax1 = 0.f, ad1 = 0.f, ay = 0.f, ady = 0.f, sd = 0.f;
        for (int ch = 0; ch < 256; ch += 32) {
            float dl = fexp(-g1 * (a * lm_delay[r0 + ch + lane] + b));
#pragma unroll
            for (int k2 = 0; k2 < 32; k2++) {
                float d = __shfl_sync(0xffffffff, dl, k2);
                int rr = r0 + ch + k2;
                float x0 = lm_X[rr * PD + t];
                float x1 = lm_X[rr * PD + t + 128];
                ax0 += x0; ad0 += d * x0;
                ax1 += x1; ad1 += d * x1;
                if (t < 2) {
                    float y = lm_Y[rr * 2 + t];
                    ay += y; ady += d * y;
                }
                sd += d;
            }
        }
        g_rp_sx[bid * PD2 + t]        = ax0;
        g_rp_sdx[bid * PD2 + t]       = ad0;
        g_rp_sx[bid * PD2 + t + 128]  = ax1;
        g_rp_sdx[bid * PD2 + t + 128] = ad1;
        if (t < 2) {
            g_rp_sx[bid * PD2 + 256 + t]  = ay;
            g_rp_sdx[bid * PD2 + 256 + t] = ady;
        }
        if (t == 0) g_rp_sd[bid] = sd;
        return;
    }
    bid -= BF_RPA;
    if (bid < BF_ROU) {         // rou0 / rou1
        int i = bid * 128 + t;
        float a = ap[0], b = bp[0], g2 = g2p[0], g3 = g3p[0];
        float x = a * tg_delay[i] + b;
        g_rou0[i] = fexp(-g2 * x);
        g_rou1[i] = fexp(-g3 * x);
        return;
    }
    bid -= BF_ROU;
    if (bid < BF_WP) {          // padded rounded w1/w2 copies
        int e = bid * 128 + t;
        if (e < 2 * PD2 * PDP) {
            int buf = e >= PD2 * PDP;
            int rem = e - buf * PD2 * PDP;
            int j = rem / PDP, k = rem - j * PDP;
            float val = (k < PD2) ? rtf32((buf ? w2_w : w1_w)[j * PD2 + k]) : 0.f;
            (buf ? g_w2p : g_w1p)[rem] = val;
        }
        return;
    }
    bid -= BF_WP;
    if (bid < BF_PQP) {         // padded rounded pq_w slice copies
        int e = bid * 128 + t;
        int buf = e >= DZ * PDP;
        int rem = e - buf * DZ * PDP;
        int j = rem / PDP, k = rem - j * PDP;
        float val = (k < PD2) ? rtf32(pq_w[j * FD + PD + buf * PD2 + k]) : 0.f;
        (buf ? g_pqcp : g_pqbp)[rem] = val;
        return;
    }
    bid -= BF_PQP;
    {                           // zero pad cols of g_Pb, g_f1p, g_f2p
        int e = bid * 128 + t;
        int buf = e / (N2 * 6);
        int rem = e - buf * (N2 * 6);
        int r = rem / 6, k = PD2 + rem - r * 6;
        float* ptr = (buf == 0) ? g_Pb : (buf == 1) ? g_f1p : g_f2p;
        ptr[r * PDP + k] = 0.f;
    }
}

// ---------------- 128x128 machinery (pre-rounded operands, no CVT) ----------
__device__ __forceinline__ void load_stage128T(
    const float* __restrict__ A, int lda, const float* __restrict__ B, int ldb,
    float* AsB, float* BsB, int m0, int n0, int N, int K, int kt, int st, int tid)
{
    int k0 = kt * BKT;
    float* as = AsB + st * BM * AST;
#pragma unroll
    for (int p = 0; p < 2; p++) {
        int c = tid + 256 * p;
        int row = c >> 2, kq = (c & 3) * 4;
        cp16(as + row * AST + kq, A + (size_t)(m0 + row) * lda + k0 + kq, (k0 + kq) < K);
    }
    float* bs = BsB + st * BN * AST;
#pragma unroll
    for (int p = 0; p < 2; p++) {
        int c = tid + 256 * p;
        int row = c >> 2, kq = (c & 3) * 4;
        bool v = (n0 + row) < N && (k0 + kq) < K;
        cp16(bs + row * AST + kq, B + (size_t)(n0 + row) * ldb + k0 + kq, v);
    }
    cp_commit();
}

__device__ __forceinline__ void mma_ktileT(
    const float* as, const float* bsT,
    int wm, int wn, int g, int tig, float acc[4][4][4])
{
#pragma unroll
    for (int ks = 0; ks < 2; ks++) {
        unsigned af[4][4], bf[4][2];
#pragma unroll
        for (int mi = 0; mi < 4; mi++) {
            const float* pa = as + (wm + mi * 16 + g) * AST + ks * 8 + tig;
            af[mi][0] = __float_as_uint(pa[0]);
            af[mi][1] = __float_as_uint(pa[8 * AST]);
            af[mi][2] = __float_as_uint(pa[4]);
            af[mi][3] = __float_as_uint(pa[8 * AST + 4]);
        }
#pragma unroll
        for (int ni = 0; ni < 4; ni++) {
            const float* pb = bsT + (wn + ni * 8 + g) * AST + ks * 8 + tig;
            bf[ni][0] = __float_as_uint(pb[0]);
            bf[ni][1] = __float_as_uint(pb[4]);
        }
#pragma unroll
        for (int mi = 0; mi < 4; mi++)
#pragma unroll
            for (int ni = 0; ni < 4; ni++) {
                asm volatile(
                    "mma.sync.aligned.m16n8k8.row.col.f32.tf32.tf32.f32 "
                    "{%0,%1,%2,%3}, {%4,%5,%6,%7}, {%8,%9}, {%0,%1,%2,%3};"
                    : "+f"(acc[mi][ni][0]), "+f"(acc[mi][ni][1]),
                      "+f"(acc[mi][ni][2]), "+f"(acc[mi][ni][3])
                    : "r"(af[mi][0]), "r"(af[mi][1]), "r"(af[mi][2]), "r"(af[mi][3]),
                      "r"(bf[ni][0]), "r"(bf[ni][1]));
            }
    }
}

__global__ void __launch_bounds__(256)
mma_gemm(const float* __restrict__ A, int lda,
         const float* __restrict__ B, int ldb,
         float* __restrict__ C, int ldc,
         int M, int N, int K, float scale)
{
    extern __shared__ float smem_dyn[];
    float* AsB = smem_dyn;
    float* BsB = smem_dyn + STAGES * BM * AST;

    const int tid = threadIdx.x;
    const int warp = tid >> 5, lane = tid & 31;
    const int g = lane >> 2, tig = lane & 3;
    const int wm = (warp & 1) * 64;
    const int wn = (warp >> 1) * 32;
    const int m0 = blockIdx.y * BM, n0 = blockIdx.x * BN;

    const int KT = (K + BKT - 1) / BKT;
    const int SPLIT = gridDim.z;
    const int KTs = (KT + SPLIT - 1) / SPLIT;
    const int kt0 = blockIdx.z * KTs;
    const int kt1 = min(KT, kt0 + KTs);
    const int nk = kt1 - kt0;

    float acc[4][4][4];
#pragma unroll
    for (int i = 0; i < 4; i++)
#pragma unroll
        for (int j = 0; j < 4; j++)
#pragma unroll
            for (int c = 0; c < 4; c++) acc[i][j][c] = 0.f;

#pragma unroll
    for (int s = 0; s < STAGES - 1; s++) {
        if (s < nk) load_stage128T(A, lda, B, ldb, AsB, BsB, m0, n0, N, K, kt0 + s, s, tid);
        else cp_commit();
    }

    for (int i = 0; i < nk; i++) {
        cp_wait<STAGES - 2>();
        __syncthreads();
        int j = i + STAGES - 1;
        if (j < nk) load_stage128T(A, lda, B, ldb, AsB, BsB, m0, n0, N, K, kt0 + j, j & (STAGES - 1), tid);
        else cp_commit();
        const int st = i & (STAGES - 1);
        mma_ktileT(AsB + st * BM * AST, BsB + st * BN * AST, wm, wn, g, tig, acc);
    }

    float* outp = (gridDim.z > 1) ? (C + (size_t)blockIdx.z * M * N) : C;
#pragma unroll
    for (int mi = 0; mi < 4; mi++) {
        int mrow0 = m0 + wm + mi * 16 + g;
#pragma unroll
        for (int ni = 0; ni < 4; ni++) {
            int ncol = n0 + wn + ni * 8 + 2 * tig;
#pragma unroll
            for (int h = 0; h < 2; h++) {
                int mr = mrow0 + h * 8;
                if (ncol < N) {
                    *(float2*)(outp + (size_t)mr * ldc + ncol) =
                        make_float2(acc[mi][ni][h*2+0] * scale, acc[mi][ni][h*2+1] * scale);
                }
            }
        }
    }
}

// ---------------- scores2 GEMM + split softmax*v epilogue ----------------
__global__ void __launch_bounds__(256)
k_score2(const float* __restrict__ A, int lda,
         const float* __restrict__ B, int ldb,
         float* __restrict__ part, int K)
{
    extern __shared__ float smem_dyn[];
    float* AsB = smem_dyn;
    float* BsB = smem_dyn + STAGES * BM * AST;

    const int tid = threadIdx.x;
    const int warp = tid >> 5, lane = tid & 31;
    const int g = lane >> 2, tig = lane & 3;
    const int wm = (warp & 1) * 64;
    const int wn = (warp >> 1) * 32;
    const int m0 = blockIdx.y * BM, n0 = blockIdx.x * BN;
    const int KT = K / BKT;

    float acc[4][4][4];
#pragma unroll
    for (int i = 0; i < 4; i++)
#pragma unroll
        for (int j = 0; j < 4; j++)
#pragma unroll
            for (int c = 0; c < 4; c++) acc[i][j][c] = 0.f;

#pragma unroll
    for (int s = 0; s < STAGES - 1; s++) {
        if (s < KT) load_stage128T(A, lda, B, ldb, AsB, BsB, m0, n0, N1, K, s, s, tid);
        else cp_commit();
    }
    for (int i = 0; i < KT; i++) {
        cp_wait<STAGES - 2>();
        __syncthreads();
        int j = i + STAGES - 1;
        if (j < KT) load_stage128T(A, lda, B, ldb, AsB, BsB, m0, n0, N1, K, j, j & (STAGES - 1), tid);
        else cp_commit();
        const int st = i & (STAGES - 1);
        mma_ktileT(AsB + st * BM * AST, BsB + st * BN * AST, wm, wn, g, tig, acc);
    }

    float v2x[4][2], v2y[4][2];
#pragma unroll
    for (int ni = 0; ni < 4; ni++) {
#pragma unroll
        for (int w = 0; w < 2; w++) {
            int gc = n0 + wn + ni * 8 + 2 * tig + w;
            v2x[ni][w] = g_v2[2 * gc];
            v2y[ni][w] = g_v2[2 * gc + 1];
        }
    }

    __syncthreads();
    float* sred = smem_dyn;
    const int w2 = warp >> 1;
#pragma unroll
    for (int mi = 0; mi < 4; mi++) {
#pragma unroll
        for (int h = 0; h < 2; h++) {
            int rloc = wm + mi * 16 + g + 8 * h;
            float m = -1e30f;
#pragma unroll
            for (int ni = 0; ni < 4; ni++)
#pragma unroll
                for (int w = 0; w < 2; w++)
                    m = fmaxf(m, acc[mi][ni][h * 2 + w] * INV_TEMP);
            float sw = 0.f, s0 = 0.f, s1 = 0.f;
#pragma unroll
            for (int ni = 0; ni < 4; ni++)
#pragma unroll
                for (int w = 0; w < 2; w++) {
                    float e = fexp(acc[mi][ni][h * 2 + w] * INV_TEMP - m);
                    sw += e;
                    s0 += e * v2x[ni][w];
                    s1 += e * v2y[ni][w];
                }
#pragma unroll
            for (int off = 1; off < 4; off <<= 1) {
                float om  = __shfl_xor_sync(0xffffffff, m,  off);
                float osw = __shfl_xor_sync(0xffffffff, sw, off);
                float os0 = __shfl_xor_sync(0xffffffff, s0, off);
                float os1 = __shfl_xor_sync(0xffffffff, s1, off);
                float nm = fmaxf(m, om);
                float ea = fexp(m - nm), eb = fexp(om - nm);
                sw = sw * ea + osw * eb;
                s0 = s0 * ea + os0 * eb;
                s1 = s1 * ea + os1 * eb;
                m = nm;
            }
            if (tig == 0) {
                float* p = sred + ((w2 * BM) + rloc) * 4;
                p[0] = m; p[1] = sw; p[2] = s0; p[3] = s1;
            }
        }
    }
    __syncthreads();

    if (tid < BM) {
        float m = -1e30f, sw = 0.f, s0 = 0.f, s1 = 0.f;
#pragma unroll
        for (int w = 0; w < 4; w++) {
            const float* p = sred + ((w * BM) + tid) * 4;
            float om = p[0], osw = p[1], os0 = p[2], os1 = p[3];
            float nm = fmaxf(m, om);
            float ea = fexp(m - nm), eb = fexp(om - nm);
            sw = sw * ea + osw * eb;
            s0 = s0 * ea + os0 * eb;
            s1 = s1 * ea + os1 * eb;
            m = nm;
        }
        float* p = part + ((size_t)blockIdx.x * N2 + (m0 + tid)) * 4;
        p[0] = m; p[1] = sw; p[2] = s0; p[3] = s1;
    }
}

__global__ void k_comb2(const float* __restrict__ part, float* __restrict__ out) {
    int r = blockIdx.x * blockDim.x + threadIdx.x;
    if (r < N2) {
        float m = -1e30f, sw = 0.f, s0 = 0.f, s1 = 0.f;
        for (int cb = 0; cb < 32; cb++) {
            const float* p = part + ((size_t)cb * N2 + r) * 4;
            float om = p[0], osw = p[1], os0 = p[2], os1 = p[3];
            float nm = fmaxf(m, om);
            float ea = fexp(m - nm), eb = fexp(om - nm);
            sw = sw * ea + osw * eb;
            s0 = s0 * ea + os0 * eb;
            s1 = s1 * ea + os1 * eb;
            m = nm;
        }
        out[2 * r]     = s0 / sw;
        out[2 * r + 1] = s1 / sw;
    }
}

// ---------------- attention 1 softmax (rounded store) + attr@lm_Y -----------
__global__ void k_attr(const float* __restrict__ lm_Y) {
    __shared__ float red[256];
    int t = threadIdx.x;
    if (blockIdx.x == N2) {
        float sd = 0.f;
#pragma unroll
        for (int rb = 0; rb < 16; rb++) sd += g_rp_sd[rb];
        for (int c = t; c < PD2; c += 256) {
            float sx = 0.f, sdx = 0.f;
#pragma unroll
            for (int rb = 0; rb < 16; rb++) {
                sx  += g_rp_sx[rb * PD2 + c];
                sdx += g_rp_sdx[rb * PD2 + c];
            }
            float r0v = sx * (1.0f / N1);
            g_router0[c] = r0v;
            g_routerp[c] = (sdx + r0v) / (1.f + sd + EPSF);
        }
        return;
    }
    int r = blockIdx.x;
    float* s = g_S + (size_t)r * N1;
    float e[16];
    float m = -1e30f;
#pragma unroll
    for (int i = 0; i < 4; i++) {
        float4 v = *(const float4*)(s + t * 4 + i * 1024);
        e[i*4+0] = v.x; e[i*4+1] = v.y; e[i*4+2] = v.z; e[i*4+3] = v.w;
        m = fmaxf(fmaxf(fmaxf(m, v.x), fmaxf(v.y, v.z)), v.w);
    }
    m = blk_max<256>(m, red);
    float z = 0.f;
#pragma unroll
    for (int i = 0; i < 16; i++) { e[i] = fexp(e[i] - m); z += e[i]; }
    z = blk_sum<256>(z, red);
    float inv = 1.f / z;
    float rs = 0.f, ry0 = 0.f, ry1 = 0.f;
#pragma unroll
    for (int i = 0; i < 4; i++) {
        int base = t * 4 + i * 1024;
        float4 v;
        v.x = fexp(e[i*4+0] * inv);
        v.y = fexp(e[i*4+1] * inv);
        v.z = fexp(e[i*4+2] * inv);
        v.w = fexp(e[i*4+3] * inv);
        float4 vr = make_float4(rtf32(v.x), rtf32(v.y), rtf32(v.z), rtf32(v.w));
        *(float4*)(s + base) = vr;
        rs += v.x + v.y + v.z + v.w;
        float4 y01 = *(const float4*)(lm_Y + base * 2);
        float4 y23 = *(const float4*)(lm_Y + base * 2 + 4);
        ry0 += v.x * y01.x + v.y * y01.z + v.z * y23.x + v.w * y23.z;
        ry1 += v.x * y01.y + v.y * y01.w + v.z * y23.y + v.w * y23.w;
    }
    rs  = blk_sum<256>(rs, red);
    ry0 = blk_sum<256>(ry0, red);
    ry1 = blk_sum<256>(ry1, red);
    if (t == 0) {
        g_asum[r] = rs;
        g_ry[2 * r]     = ry0;
        g_ry[2 * r + 1] = ry1;
    }
}

// ---------------- fused reduce(split-8) + prop0 -> g_Pa (padded, rounded) -----
__global__ void k_fuse1(const float* __restrict__ part, const float* __restrict__ tg_X,
                        const float* __restrict__ w1_w, const float* __restrict__ w1_b) {
    if (blockIdx.x == 2112) {            // router1
        int t = threadIdx.x;
        int warp = t >> 5, lane = t & 31;
        for (int j = warp; j < PD2; j += 8) {
            float s = 0.f;
            for (int k = lane; k < PD2; k += 32) s += g_routerp[k] * w1_w[j * PD2 + k];
#pragma unroll
            for (int off = 16; off > 0; off >>= 1) s += __shfl_xor_sync(0xffffffff, s, off);
            if (lane == 0) g_router1[j] = s + w1_b[j];
        }
        return;
    }
    int i = blockIdx.x * blockDim.x + threadIdx.x;   // i < 2048*264
    int r = i / PDP, c = i - r * PDP;
    float v;
    if (c < PD) {
        float s = 0.f;
#pragma unroll
        for (int z = 0; z < 8; z++) s += part[(size_t)z * N2 * PD + r * PD + c];
        s += tg_X[r * PD + c];
        v = rtf32((s + g_rou0[r] * g_router0[c]) / (1.f + g_asum[r] + g_rou0[r] + EPSF));
    } else if (c < PD2) {
        float s = g_ry[2 * r + (c - PD)];
        v = rtf32((s + g_rou0[r] * g_router0[c]) / (1.f + g_asum[r] + g_rou0[r] + EPSF));
    } else {
        v = 0.f;
    }
    g_Pa[i] = v;
}

// ---------------- 64-tile wrappers ----------------
__global__ void __launch_bounds__(128)
k_f1(const float* __restrict__ w1_b, float* __restrict__ out) {
    extern __shared__ float smem_dyn[];
    int bx = blockIdx.x % 5, by = blockIdx.x / 5;
    gemm64_body<false>(g_Pa, PDP, g_w1p, PDP, w1_b, out + N2 * 2 + PD, FD,
                       PD2, PD2, PDP, 1.f,
                       g_rou1, g_router1, g_Pb, g_f1p, nullptr, nullptr,
                       false, bx, by, smem_dyn);
}

__global__ void __launch_bounds__(128)
k_mid(const float* __restrict__ w2_b, float* __restrict__ out) {
    extern __shared__ float smem_dyn[];
    if (blockIdx.x < 160) {              // f2
        int bx = blockIdx.x % 5, by = blockIdx.x / 5;
        gemm64_body<false>(g_Pb, PDP, g_w2p, PDP, w2_b, out + N2 * 2 + PD + PD2, FD,
                           PD2, PD2, PDP, 1.f,
                           nullptr, nullptr, nullptr, g_f2p, nullptr, nullptr,
                           false, bx, by, smem_dyn);
    } else {                             // q2b = f1p @ pqbp^T
        int b = blockIdx.x - 160;
        gemm64_body<false>(g_f1p, PDP, g_pqbp, PDP, nullptr, g_q2b, DZ,
                           DZ, PD2, PDP, 1.f,
                           nullptr, nullptr, nullptr, nullptr, nullptr, nullptr,
                           false, b & 1, b >> 1, smem_dyn);
    }
}

__global__ void __launch_bounds__(128)
k_q2fin() {
    extern __shared__ float smem_dyn[];
    gemm64_body<false>(g_f2p, PDP, g_pqcp, PDP, nullptr, g_q2, DZ,
                       DZ, PD2, PDP, 1.f,
                       nullptr, nullptr, nullptr, nullptr, g_q2a, g_q2b,
                       true, blockIdx.x & 1, blockIdx.x >> 1, smem_dyn);
}

// ---------------- host launch ----------------
static float* sym_addr(const void* s) {
    void* p = nullptr;
    cudaGetSymbolAddress(&p, s);
    return (float*)p;
}

#define SMEM_TT ((STAGES * BM * AST + STAGES * BN * AST) * 4)
#define SMEM_64 ((STAGES * BM6 * AST * 2) * 4)

extern "C" void kernel_launch(void* const* d_in, const int* in_sizes, int n_in,
                              void* d_out, int out_size) {
    const float* lm_X    = (const float*)d_in[0];
    const float* lm_Y    = (const float*)d_in[1];
    const float* tg_X    = (const float*)d_in[2];
    const float* lm_delay= (const float*)d_in[4];
    const float* tg_delay= (const float*)d_in[5];
    const float* aq_w    = (const float*)d_in[6];
    const float* aq_b    = (const float*)d_in[7];
    const float* ak_w    = (const float*)d_in[8];
    const float* ak_b    = (const float*)d_in[9];
    const float* w1_w    = (const float*)d_in[10];
    const float* w1_b    = (const float*)d_in[11];
    const float* w2_w    = (const float*)d_in[12];
    const float* w2_b    = (const float*)d_in[13];
    const float* pq_w    = (const float*)d_in[14];
    const float* pq_b    = (const float*)d_in[15];
    const float* pk_w    = (const float*)d_in[16];
    const float* pk_b    = (const float*)d_in[17];
    const float* pv_w    = (const float*)d_in[18];
    const float* pv_b    = (const float*)d_in[19];
    const float* gamma1  = (const float*)d_in[20];
    const float* gamma2  = (const float*)d_in[21];
    const float* gamma3  = (const float*)d_in[22];
    const float* alpha   = (const float*)d_in[23];
    const float* beta    = (const float*)d_in[24];
    float* out = (float*)d_out;

    float* pk12  = sym_addr(g_k12);
    float* pq    = sym_addr(g_q);
    float* pq2   = sym_addr(g_q2);
    float* pS    = sym_addr(g_S);
    float* plmfT = sym_addr(g_lmfT);
    float* pPart = sym_addr(g_part);

    cudaFuncSetAttribute(mma_gemm, cudaFuncAttributeMaxDynamicSharedMemorySize, SMEM_TT);
    cudaFuncSetAttribute(k_score2, cudaFuncAttributeMaxDynamicSharedMemorySize, SMEM_TT);
    cudaFuncSetAttribute(k_front,  cudaFuncAttributeMaxDynamicSharedMemorySize, SMEM_64);
    cudaFuncSetAttribute(k_f1,     cudaFuncAttributeMaxDynamicSharedMemorySize, SMEM_64);
    cudaFuncSetAttribute(k_mid,    cudaFuncAttributeMaxDynamicSharedMemorySize, SMEM_64);
    cudaFuncSetAttribute(k_q2fin,  cudaFuncAttributeMaxDynamicSharedMemorySize, SMEM_64);

    dim3 blk(256), blk64(128);

    // 1. front mega-kernel
    k_front<<<BF_TOT, blk64, SMEM_64>>>(lm_X, lm_Y, tg_X, ak_w, ak_b, pk_w, pk_b,
                                        aq_w, aq_b, pq_w, pq_b, w1_w, w2_w,
                                        lm_delay, tg_delay,
                                        gamma1, gamma2, gamma3, alpha, beta,
                                        pv_w, pv_b, out);

    // 2. scores1 = q @ k1^T (pre-rounded operands)
    mma_gemm<<<dim3(32, 16, 1), blk, SMEM_TT>>>(pq, DZ, pk12, 2 * DZ, pS, N1, N2, N1, DZ, INV_TEMP);

    // 3. softmax -> attr (rounded) + attr@lm_Y + router combine
    k_attr<<<N2 + 1, blk>>>(lm_Y);

    // 4. attr @ lmfT[:256], split-8, no-CVT mainloop
    mma_gemm<<<dim3(2, 16, 8), blk, SMEM_TT>>>(pS, N1, plmfT, N1, pPart, PD, N2, PD, N1, 1.f);

    // 5. fused reduce(8) + prop0 -> g_Pa (+ router1)
    k_fuse1<<<2113, blk>>>(pPart, tg_X, w1_w, w1_b);

    // 6. f1 -> out, prop1 -> g_Pb, padded copy -> g_f1p
    k_f1<<<160, blk64, SMEM_64>>>(w1_b, out);

    // 7. batched f2 (+g_f2p) + q2b
    k_mid<<<224, blk64, SMEM_64>>>(w2_b, out);

    // 8. q2 = q2a + q2b + q2c (rounded)
    k_q2fin<<<64, blk64, SMEM_64>>>();

    // 9-10. attention 2 fused
    k_score2<<<dim3(32, 16, 1), blk, SMEM_TT>>>(pq2, DZ, pk12 + DZ, 2 * DZ, pPart, DZ);
    k_comb2<<<8, blk>>>(pPart, out);
}

// round 14
// speedup vs baseline: 1.1119x; 1.0239x over previous
#include <cuda_runtime.h>
#include <math.h>

// ---------------- problem constants ----------------
#define N1 4096
#define N2 2048
#define PD 256
#define DZ 128
#define PD2 258
#define PDP 264            // padded K stride (16B-aligned rows)
#define FD 772
#define EPSF 1e-12f
#define INV_TEMP 0.08838834764831843f

// PDL: wait for the predecessor grid (full completion + memory flush).
#define GDC_WAIT asm volatile("griddepcontrol.wait;" ::: "memory")

// ---------------- device scratch ----------------
__device__ float g_k12[N1 * 2 * DZ];
__device__ float g_q[N2 * DZ];
__device__ float g_q2[N2 * DZ];
__device__ float g_q2a[N2 * DZ];
__device__ float g_q2b[N2 * DZ];
__device__ float g_S[(size_t)N2 * N1];
__device__ float g_lmfT[PD2 * N1];
__device__ float g_Pa[N2 * PDP];
__device__ float g_Pb[N2 * PDP];
__device__ float g_f1p[N2 * PDP];
__device__ float g_f2p[N2 * PDP];
__device__ float g_w1p[PD2 * PDP];
__device__ float g_w2p[PD2 * PDP];
__device__ float g_pqbp[DZ * PDP];
__device__ float g_pqcp[DZ * PDP];
__device__ float g_part[8 * 2048 * 258];
__device__ float g_ry[N2 * 2];
__device__ float g_rp_sx[16 * PD2];
__device__ float g_rp_sdx[16 * PD2];
__device__ float g_rp_sd[16];
__device__ float g_router0[PD2];
__device__ float g_routerp[PD2];
__device__ float g_router1[PD2];
__device__ float g_rou0[N2];
__device__ float g_rou1[N2];
__device__ float g_asum[N2];
__device__ float g_v2[N1 * 2];

// ---------------- helpers ----------------
__device__ __forceinline__ float fexp(float x) {
    float y;
    asm("ex2.approx.f32 %0, %1;" : "=f"(y) : "f"(x * 1.4426950408889634f));
    return y;
}
__device__ __forceinline__ float rtf32(float x) {
    unsigned r;
    asm("cvt.rna.tf32.f32 %0, %1;" : "=r"(r) : "f"(x));
    return __uint_as_float(r);
}
__device__ __forceinline__ unsigned f2tf32(float x) {
    unsigned r;
    asm("cvt.rna.tf32.f32 %0, %1;" : "=r"(r) : "f"(x));
    return r;
}
__device__ __forceinline__ void cp16(float* dst, const float* src, bool valid) {
    unsigned d = (unsigned)__cvta_generic_to_shared(dst);
    int sz = valid ? 16 : 0;
    asm volatile("cp.async.cg.shared.global [%0], [%1], 16, %2;" :: "r"(d), "l"(src), "r"(sz));
}
__device__ __forceinline__ void cp_commit() { asm volatile("cp.async.commit_group;"); }
template<int N_>
__device__ __forceinline__ void cp_wait() {
    asm volatile("cp.async.wait_group %0;" :: "n"(N_));
}

template<int TB>
__device__ __forceinline__ float blk_sum(float v, float* red) {
    int t = threadIdx.x;
    red[t] = v; __syncthreads();
    for (int s = TB >> 1; s > 0; s >>= 1) {
        if (t < s) red[t] += red[t + s];
        __syncthreads();
    }
    float r = red[0]; __syncthreads();
    return r;
}
template<int TB>
__device__ __forceinline__ float blk_max(float v, float* red) {
    int t = threadIdx.x;
    red[t] = v; __syncthreads();
    for (int s = TB >> 1; s > 0; s >>= 1) {
        if (t < s) red[t] = fmaxf(red[t], red[t + s]);
        __syncthreads();
    }
    float r = red[0]; __syncthreads();
    return r;
}

// ---------------- GEMM tile configs ----------------
#define BM 128
#define BN 128
#define BKT 16
#define AST 20
#define STAGES 4
#define BM6 64
#define BN6 64

// ---------------- 64x64 tf32 GEMM body ----------------
template<bool CVT>
__device__ __forceinline__ void gemm64_body(
    const float* __restrict__ A, int lda,
    const float* __restrict__ B, int ldb,
    const float* __restrict__ bias, float* __restrict__ C, int ldc,
    int N, int K, int Kld, float scale,
    const float* __restrict__ rou1, const float* __restrict__ rt1,
    float* __restrict__ P, float* __restrict__ Cpad,
    const float* __restrict__ add1, const float* __restrict__ add2,
    bool roundC, int bx, int by, float* smem)
{
    float* AsB = smem;
    float* BsB = smem + STAGES * BM6 * AST;

    const int tid = threadIdx.x;
    const int warp = tid >> 5, lane = tid & 31;
    const int g = lane >> 2, tig = lane & 3;
    const int wm = (warp & 1) * 32;
    const int wn = (warp >> 1) * 32;
    const int m0 = by * BM6, n0 = bx * BN6;

    const int KT = (K + BKT - 1) / BKT;

    float acc[2][4][4];
#pragma unroll
    for (int i = 0; i < 2; i++)
#pragma unroll
        for (int j = 0; j < 4; j++)
#pragma unroll
            for (int c = 0; c < 4; c++) acc[i][j][c] = 0.f;

    auto loadStage = [&](int kt, int st) {
        int k0 = kt * BKT;
        float* as = AsB + st * BM6 * AST;
        float* bs = BsB + st * BN6 * AST;
#pragma unroll
        for (int p = 0; p < 2; p++) {
            int c = tid + 128 * p;
            int row = c >> 2, kq = (c & 3) * 4;
            cp16(as + row * AST + kq, A + (size_t)(m0 + row) * lda + k0 + kq, (k0 + kq) < Kld);
        }
#pragma unroll
        for (int p = 0; p < 2; p++) {
            int c = tid + 128 * p;
            int row = c >> 2, kq = (c & 3) * 4;
            bool v = (n0 + row) < N && (k0 + kq) < Kld;
            cp16(bs + row * AST + kq, B + (size_t)(n0 + row) * ldb + k0 + kq, v);
        }
        cp_commit();
    };

#pragma unroll
    for (int s = 0; s < STAGES - 1; s++) {
        if (s < KT) loadStage(s, s);
        else cp_commit();
    }

    for (int i = 0; i < KT; i++) {
        cp_wait<STAGES - 2>();
        __syncthreads();
        int j = i + STAGES - 1;
        if (j < KT) loadStage(j, j & (STAGES - 1));
        else cp_commit();
        const int st = i & (STAGES - 1);
        const float* as = AsB + st * BM6 * AST;
        const float* bs = BsB + st * BN6 * AST;

#pragma unroll
        for (int ks = 0; ks < 2; ks++) {
            unsigned af[2][4], bf[4][2];
#pragma unroll
            for (int mi = 0; mi < 2; mi++) {
                const float* pa = as + (wm + mi * 16 + g) * AST + ks * 8 + tig;
                if (CVT) {
                    af[mi][0] = f2tf32(pa[0]);
                    af[mi][1] = f2tf32(pa[8 * AST]);
                    af[mi][2] = f2tf32(pa[4]);
                    af[mi][3] = f2tf32(pa[8 * AST + 4]);
                } else {
                    af[mi][0] = __float_as_uint(pa[0]);
                    af[mi][1] = __float_as_uint(pa[8 * AST]);
                    af[mi][2] = __float_as_uint(pa[4]);
                    af[mi][3] = __float_as_uint(pa[8 * AST + 4]);
                }
            }
#pragma unroll
            for (int ni = 0; ni < 4; ni++) {
                const float* pb = bs + (wn + ni * 8 + g) * AST + ks * 8 + tig;
                if (CVT) {
                    bf[ni][0] = f2tf32(pb[0]);
                    bf[ni][1] = f2tf32(pb[4]);
                } else {
                    bf[ni][0] = __float_as_uint(pb[0]);
                    bf[ni][1] = __float_as_uint(pb[4]);
                }
            }
#pragma unroll
            for (int mi = 0; mi < 2; mi++)
#pragma unroll
                for (int ni = 0; ni < 4; ni++) {
                    asm volatile(
                        "mma.sync.aligned.m16n8k8.row.col.f32.tf32.tf32.f32 "
                        "{%0,%1,%2,%3}, {%4,%5,%6,%7}, {%8,%9}, {%0,%1,%2,%3};"
                        : "+f"(acc[mi][ni][0]), "+f"(acc[mi][ni][1]),
                          "+f"(acc[mi][ni][2]), "+f"(acc[mi][ni][3])
                        : "r"(af[mi][0]), "r"(af[mi][1]), "r"(af[mi][2]), "r"(af[mi][3]),
                          "r"(bf[ni][0]), "r"(bf[ni][1]));
                }
        }
    }

#pragma unroll
    for (int mi = 0; mi < 2; mi++) {
        int mrow0 = m0 + wm + mi * 16 + g;
#pragma unroll
        for (int ni = 0; ni < 4; ni++) {
            int ncol = n0 + wn + ni * 8 + 2 * tig;
#pragma unroll
            for (int h = 0; h < 2; h++) {
                int mr = mrow0 + h * 8;
                if (ncol < N) {
                    float2 bv = bias ? *(const float2*)(bias + ncol) : make_float2(0.f, 0.f);
                    float v0 = acc[mi][ni][h * 2 + 0] * scale + bv.x;
                    float v1 = acc[mi][ni][h * 2 + 1] * scale + bv.y;
                    if (add1) {
                        float2 a1 = *(const float2*)(add1 + (size_t)mr * ldc + ncol);
                        v0 += a1.x; v1 += a1.y;
                    }
                    if (add2) {
                        float2 a2 = *(const float2*)(add2 + (size_t)mr * ldc + ncol);
                        v0 += a2.x; v1 += a2.y;
                    }
                    float c0 = roundC ? rtf32(v0) : v0;
                    float c1 = roundC ? rtf32(v1) : v1;
                    *(float2*)(C + (size_t)mr * ldc + ncol) = make_float2(c0, c1);
                    if (Cpad) {
                        *(float2*)(Cpad + (size_t)mr * PDP + ncol) =
                            make_float2(rtf32(v0), rtf32(v1));
                    }
                    if (P) {
                        float rr = rou1[mr];
                        float inv = 1.f / (1.f + rr + EPSF);
                        *(float2*)(P + (size_t)mr * PDP + ncol) =
                            make_float2(rtf32((v0 + rr * rt1[ncol]) * inv),
                                        rtf32((v1 + rr * rt1[ncol + 1]) * inv));
                    }
                }
            }
        }
    }
}

// ---------------- front mega-kernel ----------------
#define BF_GEMM 384
#define BF_TRX  256
#define BF_TRY  64
#define BF_TGX  1024
#define BF_V2   32
#define BF_RPA  16
#define BF_ROU  16
#define BF_WP   1065
#define BF_PQP  528
#define BF_ZP   288
#define BF_TOT (BF_GEMM + BF_TRX + BF_TRY + BF_TGX + BF_V2 + BF_RPA + BF_ROU + BF_WP + BF_PQP + BF_ZP)

__global__ void __launch_bounds__(128)
k_front(const float* __restrict__ lm_X, const float* __restrict__ lm_Y,
        const float* __restrict__ tg_X,
        const float* __restrict__ ak_w, const float* __restrict__ ak_b,
        const float* __restrict__ pk_w, const float* __restrict__ pk_b,
        const float* __restrict__ aq_w, const float* __restrict__ aq_b,
        const float* __restrict__ pq_w, const float* __restrict__ pq_b,
        const float* __restrict__ w1_w, const float* __restrict__ w2_w,
        const float* __restrict__ lm_delay, const float* __restrict__ tg_delay,
        const float* g1p, const float* g2p, const float* g3p,
        const float* ap, const float* bp,
        const float* __restrict__ pv_w, const float* __restrict__ pv_b,
        float* __restrict__ out)
{
    extern __shared__ float smem_dyn[];
    int bid = blockIdx.x, t = threadIdx.x;

    if (bid < 128) {
        gemm64_body<true>(lm_X, PD, ak_w, PD, ak_b, g_k12, 2 * DZ, DZ, PD, PD, 1.f,
                          nullptr, nullptr, nullptr, nullptr, nullptr, nullptr,
                          true, bid & 1, bid >> 1, smem_dyn);
        return;
    }
    bid -= 128;
    if (bid < 128) {
        gemm64_body<true>(lm_X, PD, pk_w, PD, pk_b, g_k12 + DZ, 2 * DZ, DZ, PD, PD, 1.f,
                          nullptr, nullptr, nullptr, nullptr, nullptr, nullptr,
                          true, bid & 1, bid >> 1, smem_dyn);
        return;
    }
    bid -= 128;
    if (bid < 64) {
        gemm64_body<true>(tg_X, PD, aq_w, PD, aq_b, g_q, DZ, DZ, PD, PD, 1.f,
                          nullptr, nullptr, nullptr, nullptr, nullptr, nullptr,
                          true, bid & 1, bid >> 1, smem_dyn);
        return;
    }
    bid -= 64;
    if (bid < 64) {
        gemm64_body<true>(tg_X, PD, pq_w, FD, pq_b, g_q2a, DZ, DZ, PD, PD, 1.f,
                          nullptr, nullptr, nullptr, nullptr, nullptr, nullptr,
                          false, bid & 1, bid >> 1, smem_dyn);
        return;
    }
    bid -= 64;
    if (bid < BF_TRX) {
        float* sm = smem_dyn;
        int tr = bid >> 2, tc = bid & 3;
        int r0 = tr * 64, c0 = tc * 64;
#pragma unroll
        for (int p = 0; p < 32; p++) {
            int e = t + 128 * p;
            int i = e >> 6, j = e & 63;
            sm[i * 65 + j] = lm_X[(size_t)(r0 + i) * PD + c0 + j];
        }
        __syncthreads();
#pragma unroll
        for (int p = 0; p < 32; p++) {
            int e = t + 128 * p;
            int i = e >> 6, j = e & 63;
            g_lmfT[(size_t)(c0 + i) * N1 + r0 + j] = rtf32(sm[j * 65 + i]);
        }
        return;
    }
    bid -= BF_TRX;
    if (bid < BF_TRY) {
        int e = bid * 128 + t;
        int h = e >> 12, k = e & 4095;
        g_lmfT[(size_t)(PD + h) * N1 + k] = rtf32(lm_Y[k * 2 + h]);
        return;
    }
    bid -= BF_TRY;
    if (bid < BF_TGX) {
        int j4 = (bid * 128 + t) * 4;
        int r = j4 >> 8, c = j4 & 255;
        *(float4*)(out + N2 * 2 + r * FD + c) = *(const float4*)(tg_X + j4);
        return;
    }
    bid -= BF_TGX;
    if (bid < BF_V2) {
        int i = bid * 128 + t;
        float y0 = lm_Y[2 * i], y1 = lm_Y[2 * i + 1];
        g_v2[2 * i]     = pv_w[0] * y0 + pv_w[1] * y1 + pv_b[0];
        g_v2[2 * i + 1] = pv_w[2] * y0 + pv_w[3] * y1 + pv_b[1];
        return;
    }
    bid -= BF_V2;
    if (bid < BF_RPA) {
        int r0 = bid * 256;
        int lane = t & 31;
        float a = ap[0], b = bp[0], g1 = g1p[0];
        float ax0 = 0.f, ad0 = 0.f, ax1 = 0.f, ad1 = 0.f, ay = 0.f, ady = 0.f, sd = 0.f;
        for (int ch = 0; ch < 256; ch += 32) {
            float dl = fexp(-g1 * (a * lm_delay[r0 + ch + lane] + b));
#pragma unroll
            for (int k2 = 0; k2 < 32; k2++) {
                float d = __shfl_sync(0xffffffff, dl, k2);
                int rr = r0 + ch + k2;
                float x0 = lm_X[rr * PD + t];
                float x1 = lm_X[rr * PD + t + 128];
                ax0 += x0; ad0 += d * x0;
                ax1 += x1; ad1 += d * x1;
                if (t < 2) {
                    float y = lm_Y[rr * 2 + t];
                    ay += y; ady += d * y;
                }
                sd += d;
            }
        }
        g_rp_sx[bid * PD2 + t]        = ax0;
        g_rp_sdx[bid * PD2 + t]       = ad0;
        g_rp_sx[bid * PD2 + t + 128]  = ax1;
        g_rp_sdx[bid * PD2 + t + 128] = ad1;
        if (t < 2) {
            g_rp_sx[bid * PD2 + 256 + t]  = ay;
            g_rp_sdx[bid * PD2 + 256 + t] = ady;
        }
        if (t == 0) g_rp_sd[bid] = sd;
        return;
    }
    bid -= BF_RPA;
    if (bid < BF_ROU) {
        int i = bid * 128 + t;
        float a = ap[0], b = bp[0], g2 = g2p[0], g3 = g3p[0];
        float x = a * tg_delay[i] + b;
        g_rou0[i] = fexp(-g2 * x);
        g_rou1[i] = fexp(-g3 * x);
        return;
    }
    bid -= BF_ROU;
    if (bid < BF_WP) {
        int e = bid * 128 + t;
        if (e < 2 * PD2 * PDP) {
            int buf = e >= PD2 * PDP;
            int rem = e - buf * PD2 * PDP;
            int j = rem / PDP, k = rem - j * PDP;
            float val = (k < PD2) ? rtf32((buf ? w2_w : w1_w)[j * PD2 + k]) : 0.f;
            (buf ? g_w2p : g_w1p)[rem] = val;
        }
        return;
    }
    bid -= BF_WP;
    if (bid < BF_PQP) {
        int e = bid * 128 + t;
        int buf = e >= DZ * PDP;
        int rem = e - buf * DZ * PDP;
        int j = rem / PDP, k = rem - j * PDP;
        float val = (k < PD2) ? rtf32(pq_w[j * FD + PD + buf * PD2 + k]) : 0.f;
        (buf ? g_pqcp : g_pqbp)[rem] = val;
        return;
    }
    bid -= BF_PQP;
    {
        int e = bid * 128 + t;
        int buf = e / (N2 * 6);
        int rem = e - buf * (N2 * 6);
        int r = rem / 6, k = PD2 + rem - r * 6;
        float* ptr = (buf == 0) ? g_Pb : (buf == 1) ? g_f1p : g_f2p;
        ptr[r * PDP + k] = 0.f;
    }
}

// ---------------- 128x128 machinery ----------------
__device__ __forceinline__ void load_stage128T(
    const float* __restrict__ A, int lda, const float* __restrict__ B, int ldb,
    float* AsB, float* BsB, int m0, int n0, int N, int K, int kt, int st, int tid)
{
    int k0 = kt * BKT;
    float* as = AsB + st * BM * AST;
#pragma unroll
    for (int p = 0; p < 2; p++) {
        int c = tid + 256 * p;
        int row = c >> 2, kq = (c & 3) * 4;
        cp16(as + row * AST + kq, A + (size_t)(m0 + row) * lda + k0 + kq, (k0 + kq) < K);
    }
    float* bs = BsB + st * BN * AST;
#pragma unroll
    for (int p = 0; p < 2; p++) {
        int c = tid + 256 * p;
        int row = c >> 2, kq = (c & 3) * 4;
        bool v = (n0 + row) < N && (k0 + kq) < K;
        cp16(bs + row * AST + kq, B + (size_t)(n0 + row) * ldb + k0 + kq, v);
    }
    cp_commit();
}

__device__ __forceinline__ void mma_ktileT(
    const float* as, const float* bsT,
    int wm, int wn, int g, int tig, float acc[4][4][4])
{
#pragma unroll
    for (int ks = 0; ks < 2; ks++) {
        unsigned af[4][4], bf[4][2];
#pragma unroll
        for (int mi = 0; mi < 4; mi++) {
            const float* pa = as + (wm + mi * 16 + g) * AST + ks * 8 + tig;
            af[mi][0] = __float_as_uint(pa[0]);
            af[mi][1] = __float_as_uint(pa[8 * AST]);
            af[mi][2] = __float_as_uint(pa[4]);
            af[mi][3] = __float_as_uint(pa[8 * AST + 4]);
        }
#pragma unroll
        for (int ni = 0; ni < 4; ni++) {
            const float* pb = bsT + (wn + ni * 8 + g) * AST + ks * 8 + tig;
            bf[ni][0] = __float_as_uint(pb[0]);
            bf[ni][1] = __float_as_uint(pb[4]);
        }
#pragma unroll
        for (int mi = 0; mi < 4; mi++)
#pragma unroll
            for (int ni = 0; ni < 4; ni++) {
                asm volatile(
                    "mma.sync.aligned.m16n8k8.row.col.f32.tf32.tf32.f32 "
                    "{%0,%1,%2,%3}, {%4,%5,%6,%7}, {%8,%9}, {%0,%1,%2,%3};"
                    : "+f"(acc[mi][ni][0]), "+f"(acc[mi][ni][1]),
                      "+f"(acc[mi][ni][2]), "+f"(acc[mi][ni][3])
                    : "r"(af[mi][0]), "r"(af[mi][1]), "r"(af[mi][2]), "r"(af[mi][3]),
                      "r"(bf[ni][0]), "r"(bf[ni][1]));
            }
    }
}

__global__ void __launch_bounds__(256)
mma_gemm(const float* __restrict__ A, int lda,
         const float* __restrict__ B, int ldb,
         float* __restrict__ C, int ldc,
         int M, int N, int K, float scale)
{
    GDC_WAIT;
    extern __shared__ float smem_dyn[];
    float* AsB = smem_dyn;
    float* BsB = smem_dyn + STAGES * BM * AST;

    const int tid = threadIdx.x;
    const int warp = tid >> 5, lane = tid & 31;
    const int g = lane >> 2, tig = lane & 3;
    const int wm = (warp & 1) * 64;
    const int wn = (warp >> 1) * 32;
    const int m0 = blockIdx.y * BM, n0 = blockIdx.x * BN;

    const int KT = (K + BKT - 1) / BKT;
    const int SPLIT = gridDim.z;
    const int KTs = (KT + SPLIT - 1) / SPLIT;
    const int kt0 = blockIdx.z * KTs;
    const int kt1 = min(KT, kt0 + KTs);
    const int nk = kt1 - kt0;

    float acc[4][4][4];
#pragma unroll
    for (int i = 0; i < 4; i++)
#pragma unroll
        for (int j = 0; j < 4; j++)
#pragma unroll
            for (int c = 0; c < 4; c++) acc[i][j][c] = 0.f;

#pragma unroll
    for (int s = 0; s < STAGES - 1; s++) {
        if (s < nk) load_stage128T(A, lda, B, ldb, AsB, BsB, m0, n0, N, K, kt0 + s, s, tid);
        else cp_commit();
    }

    for (int i = 0; i < nk; i++) {
        cp_wait<STAGES - 2>();
        __syncthreads();
        int j = i + STAGES - 1;
        if (j < nk) load_stage128T(A, lda, B, ldb, AsB, BsB, m0, n0, N, K, kt0 + j, j & (STAGES - 1), tid);
        else cp_commit();
        const int st = i & (STAGES - 1);
        mma_ktileT(AsB + st * BM * AST, BsB + st * BN * AST, wm, wn, g, tig, acc);
    }

    float* outp = (gridDim.z > 1) ? (C + (size_t)blockIdx.z * M * N) : C;
#pragma unroll
    for (int mi = 0; mi < 4; mi++) {
        int mrow0 = m0 + wm + mi * 16 + g;
#pragma unroll
        for (int ni = 0; ni < 4; ni++) {
            int ncol = n0 + wn + ni * 8 + 2 * tig;
#pragma unroll
            for (int h = 0; h < 2; h++) {
                int mr = mrow0 + h * 8;
                if (ncol < N) {
                    *(float2*)(outp + (size_t)mr * ldc + ncol) =
                        make_float2(acc[mi][ni][h*2+0] * scale, acc[mi][ni][h*2+1] * scale);
                }
            }
        }
    }
}

// ---------------- scores2 GEMM + split softmax*v epilogue ----------------
__global__ void __launch_bounds__(256)
k_score2(const float* __restrict__ A, int lda,
         const float* __restrict__ B, int ldb,
         float* __restrict__ part, int K)
{
    GDC_WAIT;
    extern __shared__ float smem_dyn[];
    float* AsB = smem_dyn;
    float* BsB = smem_dyn + STAGES * BM * AST;

    const int tid = threadIdx.x;
    const int warp = tid >> 5, lane = tid & 31;
    const int g = lane >> 2, tig = lane & 3;
    const int wm = (warp & 1) * 64;
    const int wn = (warp >> 1) * 32;
    const int m0 = blockIdx.y * BM, n0 = blockIdx.x * BN;
    const int KT = K / BKT;

    float acc[4][4][4];
#pragma unroll
    for (int i = 0; i < 4; i++)
#pragma unroll
        for (int j = 0; j < 4; j++)
#pragma unroll
            for (int c = 0; c < 4; c++) acc[i][j][c] = 0.f;

#pragma unroll
    for (int s = 0; s < STAGES - 1; s++) {
        if (s < KT) load_stage128T(A, lda, B, ldb, AsB, BsB, m0, n0, N1, K, s, s, tid);
        else cp_commit();
    }
    for (int i = 0; i < KT; i++) {
        cp_wait<STAGES - 2>();
        __syncthreads();
        int j = i + STAGES - 1;
        if (j < KT) load_stage128T(A, lda, B, ldb, AsB, BsB, m0, n0, N1, K, j, j & (STAGES - 1), tid);
        else cp_commit();
        const int st = i & (STAGES - 1);
        mma_ktileT(AsB + st * BM * AST, BsB + st * BN * AST, wm, wn, g, tig, acc);
    }

    float v2x[4][2], v2y[4][2];
#pragma unroll
    for (int ni = 0; ni < 4; ni++) {
#pragma unroll
        for (int w = 0; w < 2; w++) {
            int gc = n0 + wn + ni * 8 + 2 * tig + w;
            v2x[ni][w] = g_v2[2 * gc];
            v2y[ni][w] = g_v2[2 * gc + 1];
        }
    }

    __syncthreads();
    float* sred = smem_dyn;
    const int w2 = warp >> 1;
#pragma unroll
    for (int mi = 0; mi < 4; mi++) {
#pragma unroll
        for (int h = 0; h < 2; h++) {
            int rloc = wm + mi * 16 + g + 8 * h;
            float m = -1e30f;
#pragma unroll
            for (int ni = 0; ni < 4; ni++)
#pragma unroll
                for (int w = 0; w < 2; w++)
                    m = fmaxf(m, acc[mi][ni][h * 2 + w] * INV_TEMP);
            float sw = 0.f, s0 = 0.f, s1 = 0.f;
#pragma unroll
            for (int ni = 0; ni < 4; ni++)
#pragma unroll
                for (int w = 0; w < 2; w++) {
                    float e = fexp(acc[mi][ni][h * 2 + w] * INV_TEMP - m);
                    sw += e;
                    s0 += e * v2x[ni][w];
                    s1 += e * v2y[ni][w];
                }
#pragma unroll
            for (int off = 1; off < 4; off <<= 1) {
                float om  = __shfl_xor_sync(0xffffffff, m,  off);
                float osw = __shfl_xor_sync(0xffffffff, sw, off);
                float os0 = __shfl_xor_sync(0xffffffff, s0, off);
                float os1 = __shfl_xor_sync(0xffffffff, s1, off);
                float nm = fmaxf(m, om);
                float ea = fexp(m - nm), eb = fexp(om - nm);
                sw = sw * ea + osw * eb;
                s0 = s0 * ea + os0 * eb;
                s1 = s1 * ea + os1 * eb;
                m = nm;
            }
            if (tig == 0) {
                float* p = sred + ((w2 * BM) + rloc) * 4;
                p[0] = m; p[1] = sw; p[2] = s0; p[3] = s1;
            }
        }
    }
    __syncthreads();

    if (tid < BM) {
        float m = -1e30f, sw = 0.f, s0 = 0.f, s1 = 0.f;
#pragma unroll
        for (int w = 0; w < 4; w++) {
            const float* p = sred + ((w * BM) + tid) * 4;
            float om = p[0], osw = p[1], os0 = p[2], os1 = p[3];
            float nm = fmaxf(m, om);
            float ea = fexp(m - nm), eb = fexp(om - nm);
            sw = sw * ea + osw * eb;
            s0 = s0 * ea + os0 * eb;
            s1 = s1 * ea + os1 * eb;
            m = nm;
        }
        float* p = part + ((size_t)blockIdx.x * N2 + (m0 + tid)) * 4;
        p[0] = m; p[1] = sw; p[2] = s0; p[3] = s1;
    }
}

__global__ void k_comb2(const float* __restrict__ part, float* __restrict__ out) {
    GDC_WAIT;
    int r = blockIdx.x * blockDim.x + threadIdx.x;
    if (r < N2) {
        float m = -1e30f, sw = 0.f, s0 = 0.f, s1 = 0.f;
        for (int cb = 0; cb < 32; cb++) {
            const float* p = part + ((size_t)cb * N2 + r) * 4;
            float om = p[0], osw = p[1], os0 = p[2], os1 = p[3];
            float nm = fmaxf(m, om);
            float ea = fexp(m - nm), eb = fexp(om - nm);
            sw = sw * ea + osw * eb;
            s0 = s0 * ea + os0 * eb;
            s1 = s1 * ea + os1 * eb;
            m = nm;
        }
        out[2 * r]     = s0 / sw;
        out[2 * r + 1] = s1 / sw;
    }
}

// ---------------- attention 1 softmax (rounded store) + attr@lm_Y -----------
__global__ void k_attr(const float* __restrict__ lm_Y) {
    GDC_WAIT;
    __shared__ float red[256];
    int t = threadIdx.x;
    if (blockIdx.x == N2) {
        float sd = 0.f;
#pragma unroll
        for (int rb = 0; rb < 16; rb++) sd += g_rp_sd[rb];
        for (int c = t; c < PD2; c += 256) {
            float sx = 0.f, sdx = 0.f;
#pragma unroll
            for (int rb = 0; rb < 16; rb++) {
                sx  += g_rp_sx[rb * PD2 + c];
                sdx += g_rp_sdx[rb * PD2 + c];
            }
            float r0v = sx * (1.0f / N1);
            g_router0[c] = r0v;
            g_routerp[c] = (sdx + r0v) / (1.f + sd + EPSF);
        }
        return;
    }
    int r = blockIdx.x;
    float* s = g_S + (size_t)r * N1;
    float e[16];
    float m = -1e30f;
#pragma unroll
    for (int i = 0; i < 4; i++) {
        float4 v = *(const float4*)(s + t * 4 + i * 1024);
        e[i*4+0] = v.x; e[i*4+1] = v.y; e[i*4+2] = v.z; e[i*4+3] = v.w;
        m = fmaxf(fmaxf(fmaxf(m, v.x), fmaxf(v.y, v.z)), v.w);
    }
    m = blk_max<256>(m, red);
    float z = 0.f;
#pragma unroll
    for (int i = 0; i < 16; i++) { e[i] = fexp(e[i] - m); z += e[i]; }
    z = blk_sum<256>(z, red);
    float inv = 1.f / z;
    float rs = 0.f, ry0 = 0.f, ry1 = 0.f;
#pragma unroll
    for (int i = 0; i < 4; i++) {
        int base = t * 4 + i * 1024;
        float4 v;
        v.x = fexp(e[i*4+0] * inv);
        v.y = fexp(e[i*4+1] * inv);
        v.z = fexp(e[i*4+2] * inv);
        v.w = fexp(e[i*4+3] * inv);
        float4 vr = make_float4(rtf32(v.x), rtf32(v.y), rtf32(v.z), rtf32(v.w));
        *(float4*)(s + base) = vr;
        rs += v.x + v.y + v.z + v.w;
        float4 y01 = *(const float4*)(lm_Y + base * 2);
        float4 y23 = *(const float4*)(lm_Y + base * 2 + 4);
        ry0 += v.x * y01.x + v.y * y01.z + v.z * y23.x + v.w * y23.z;
        ry1 += v.x * y01.y + v.y * y01.w + v.z * y23.y + v.w * y23.w;
    }
    rs  = blk_sum<256>(rs, red);
    ry0 = blk_sum<256>(ry0, red);
    ry1 = blk_sum<256>(ry1, red);
    if (t == 0) {
        g_asum[r] = rs;
        g_ry[2 * r]     = ry0;
        g_ry[2 * r + 1] = ry1;
    }
}

// ---------------- fused reduce(split-8) + prop0 (+router1 block) --------------
__global__ void k_fuse1(const float* __restrict__ part, const float* __restrict__ tg_X,
                        const float* __restrict__ w1_w, const float* __restrict__ w1_b) {
    GDC_WAIT;
    if (blockIdx.x == 2112) {
        int t = threadIdx.x;
        int warp = t >> 5, lane = t & 31;
        for (int j = warp; j < PD2; j += 8) {
            float s = 0.f;
            for (int k = lane; k < PD2; k += 32) s += g_routerp[k] * w1_w[j * PD2 + k];
#pragma unroll
            for (int off = 16; off > 0; off >>= 1) s += __shfl_xor_sync(0xffffffff, s, off);
            if (lane == 0) g_router1[j] = s + w1_b[j];
        }
        return;
    }
    int i = blockIdx.x * blockDim.x + threadIdx.x;
    int r = i / PDP, c = i - r * PDP;
    float v;
    if (c < PD) {
        float s = 0.f;
#pragma unroll
        for (int z = 0; z < 8; z++) s += part[(size_t)z * N2 * PD + r * PD + c];
        s += tg_X[r * PD + c];
        v = rtf32((s + g_rou0[r] * g_router0[c]) / (1.f + g_asum[r] + g_rou0[r] + EPSF));
    } else if (c < PD2) {
        float s = g_ry[2 * r + (c - PD)];
        v = rtf32((s + g_rou0[r] * g_router0[c]) / (1.f + g_asum[r] + g_rou0[r] + EPSF));
    } else {
        v = 0.f;
    }
    g_Pa[i] = v;
}

// ---------------- 64-tile wrappers ----------------
__global__ void __launch_bounds__(128)
k_f1(const float* __restrict__ w1_b, float* __restrict__ out) {
    GDC_WAIT;
    extern __shared__ float smem_dyn[];
    int bx = blockIdx.x % 5, by = blockIdx.x / 5;
    gemm64_body<false>(g_Pa, PDP, g_w1p, PDP, w1_b, out + N2 * 2 + PD, FD,
                       PD2, PD2, PDP, 1.f,
                       g_rou1, g_router1, g_Pb, g_f1p, nullptr, nullptr,
                       false, bx, by, smem_dyn);
}

__global__ void __launch_bounds__(128)
k_mid(const float* __restrict__ w2_b, float* __restrict__ out) {
    GDC_WAIT;
    extern __shared__ float smem_dyn[];
    if (blockIdx.x < 160) {
        int bx = blockIdx.x % 5, by = blockIdx.x / 5;
        gemm64_body<false>(g_Pb, PDP, g_w2p, PDP, w2_b, out + N2 * 2 + PD + PD2, FD,
                           PD2, PD2, PDP, 1.f,
                           nullptr, nullptr, nullptr, g_f2p, nullptr, nullptr,
                           false, bx, by, smem_dyn);
    } else {
        int b = blockIdx.x - 160;
        gemm64_body<false>(g_f1p, PDP, g_pqbp, PDP, nullptr, g_q2b, DZ,
                           DZ, PD2, PDP, 1.f,
                           nullptr, nullptr, nullptr, nullptr, nullptr, nullptr,
                           false, b & 1, b >> 1, smem_dyn);
    }
}

__global__ void __launch_bounds__(128)
k_q2fin() {
    GDC_WAIT;
    extern __shared__ float smem_dyn[];
    gemm64_body<false>(g_f2p, PDP, g_pqcp, PDP, nullptr, g_q2, DZ,
                       DZ, PD2, PDP, 1.f,
                       nullptr, nullptr, nullptr, nullptr, g_q2a, g_q2b,
                       true, blockIdx.x & 1, blockIdx.x >> 1, smem_dyn);
}

// ---------------- host launch ----------------
static float* sym_addr(const void* s) {
    void* p = nullptr;
    cudaGetSymbolAddress(&p, s);
    return (float*)p;
}

#define SMEM_TT ((STAGES * BM * AST + STAGES * BN * AST) * 4)
#define SMEM_64 ((STAGES * BM6 * AST * 2) * 4)

template<typename F, typename... Args>
static void pdl_launch(dim3 g, dim3 b, size_t sh, F f, Args... args) {
    cudaLaunchConfig_t cfg = {};
    cfg.gridDim = g;
    cfg.blockDim = b;
    cfg.dynamicSmemBytes = sh;
    cfg.stream = 0;
    cudaLaunchAttribute at[1];
    at[0].id = cudaLaunchAttributeProgrammaticStreamSerialization;
    at[0].val.programmaticStreamSerializationAllowed = 1;
    cfg.attrs = at;
    cfg.numAttrs = 1;
    cudaLaunchKernelEx(&cfg, f, args...);
}

extern "C" void kernel_launch(void* const* d_in, const int* in_sizes, int n_in,
                              void* d_out, int out_size) {
    const float* lm_X    = (const float*)d_in[0];
    const float* lm_Y    = (const float*)d_in[1];
    const float* tg_X    = (const float*)d_in[2];
    const float* lm_delay= (const float*)d_in[4];
    const float* tg_delay= (const float*)d_in[5];
    const float* aq_w    = (const float*)d_in[6];
    const float* aq_b    = (const float*)d_in[7];
    const float* ak_w    = (const float*)d_in[8];
    const float* ak_b    = (const float*)d_in[9];
    const float* w1_w    = (const float*)d_in[10];
    const float* w1_b    = (const float*)d_in[11];
    const float* w2_w    = (const float*)d_in[12];
    const float* w2_b    = (const float*)d_in[13];
    const float* pq_w    = (const float*)d_in[14];
    const float* pq_b    = (const float*)d_in[15];
    const float* pk_w    = (const float*)d_in[16];
    const float* pk_b    = (const float*)d_in[17];
    const float* pv_w    = (const float*)d_in[18];
    const float* pv_b    = (const float*)d_in[19];
    const float* gamma1  = (const float*)d_in[20];
    const float* gamma2  = (const float*)d_in[21];
    const float* gamma3  = (const float*)d_in[22];
    const float* alpha   = (const float*)d_in[23];
    const float* beta    = (const float*)d_in[24];
    float* out = (float*)d_out;

    float* pk12  = sym_addr(g_k12);
    float* pq    = sym_addr(g_q);
    float* pq2   = sym_addr(g_q2);
    float* pS    = sym_addr(g_S);
    float* plmfT = sym_addr(g_lmfT);
    float* pPart = sym_addr(g_part);

    cudaFuncSetAttribute(mma_gemm, cudaFuncAttributeMaxDynamicSharedMemorySize, SMEM_TT);
    cudaFuncSetAttribute(k_score2, cudaFuncAttributeMaxDynamicSharedMemorySize, SMEM_TT);
    cudaFuncSetAttribute(k_front,  cudaFuncAttributeMaxDynamicSharedMemorySize, SMEM_64);
    cudaFuncSetAttribute(k_f1,     cudaFuncAttributeMaxDynamicSharedMemorySize, SMEM_64);
    cudaFuncSetAttribute(k_mid,    cudaFuncAttributeMaxDynamicSharedMemorySize, SMEM_64);
    cudaFuncSetAttribute(k_q2fin,  cudaFuncAttributeMaxDynamicSharedMemorySize, SMEM_64);

    dim3 blk(256), blk64(128);

    // 1. front mega-kernel (plain launch)
    k_front<<<BF_TOT, blk64, SMEM_64>>>(lm_X, lm_Y, tg_X, ak_w, ak_b, pk_w, pk_b,
                                        aq_w, aq_b, pq_w, pq_b, w1_w, w2_w,
                                        lm_delay, tg_delay,
                                        gamma1, gamma2, gamma3, alpha, beta,
                                        pv_w, pv_b, out);

    // 2. scores1 = q @ k1^T
    pdl_launch(dim3(32, 16, 1), blk, SMEM_TT, mma_gemm,
               (const float*)pq, DZ, (const float*)pk12, 2 * DZ, pS, N1, N2, N1, DZ, INV_TEMP);

    // 3. softmax -> attr (rounded) + attr@lm_Y + router combine
    pdl_launch(dim3(N2 + 1, 1, 1), blk, 0, k_attr, lm_Y);

    // 4. attr @ lmfT[:256], split-8
    pdl_launch(dim3(2, 16, 8), blk, SMEM_TT, mma_gemm,
               (const float*)pS, N1, (const float*)plmfT, N1, pPart, PD, N2, PD, N1, 1.f);

    // 5. fused reduce(8) + prop0 -> g_Pa (+ router1)
    pdl_launch(dim3(2113, 1, 1), blk, 0, k_fuse1, (const float*)pPart, tg_X, w1_w, w1_b);

    // 6. f1 -> out, prop1 -> g_Pb, padded copy -> g_f1p
    pdl_launch(dim3(160, 1, 1), blk64, SMEM_64, k_f1, w1_b, out);

    // 7. batched f2 (+g_f2p) + q2b
    pdl_launch(dim3(224, 1, 1), blk64, SMEM_64, k_mid, w2_b, out);

    // 8. q2 = q2a + q2b + q2c
    pdl_launch(dim3(64, 1, 1), blk64, SMEM_64, k_q2fin);

    // 9. attention 2 fused scores+softmax partials
    pdl_launch(dim3(32, 16, 1), blk, SMEM_TT, k_score2,
               (const float*)pq2, DZ, (const float*)(pk12 + DZ), 2 * DZ, pPart, DZ);

    // 10. combine
    pdl_launch(dim3(8, 1, 1), blk, 0, k_comb2, (const float*)pPart, out);
}